// round 3
// baseline (speedup 1.0000x reference)
#include <cuda_runtime.h>
#include <cuda_fp16.h>
#include <cstdint>

// ---------------------------------------------------------------------------
// Problem constants
// ---------------------------------------------------------------------------
#define BATCH 32
#define CDIM  512
#define NHEAD 16
#define SHIFT 4
#define SEQ   64
#define HEADD 32
#define FFDIM 2048
#define MTOK  131072

// ---------------------------------------------------------------------------
// Scratch
// ---------------------------------------------------------------------------
__device__ __half g_xw  [ (size_t)MTOK * CDIM  ];
__device__ __half g_qkv [ (size_t)MTOK * 3*CDIM];
__device__ __half g_attn[ (size_t)MTOK * CDIM  ];
__device__ float  g_proj[ (size_t)MTOK * CDIM  ];
__device__ float  g_x   [ (size_t)MTOK * CDIM  ];
__device__ __half g_h   [ (size_t)MTOK * CDIM  ];
__device__ __half g_ff  [ (size_t)MTOK * FFDIM ];
__device__ __half g_wqkvT[3*CDIM * CDIM];
__device__ __half g_woT  [CDIM * CDIM];
__device__ __half g_w1T  [FFDIM * CDIM];
__device__ __half g_w2T  [CDIM * FFDIM];

// ---------------------------------------------------------------------------
// Helpers
// ---------------------------------------------------------------------------
__device__ __forceinline__ void cp16(void* smem, const void* gmem) {
    unsigned s = (unsigned)__cvta_generic_to_shared(smem);
    asm volatile("cp.async.cg.shared.global [%0], [%1], 16;\n" :: "r"(s), "l"(gmem));
}
__device__ __forceinline__ void cp_commit() { asm volatile("cp.async.commit_group;\n"); }
__device__ __forceinline__ void cp_wait1()  { asm volatile("cp.async.wait_group 1;\n"); }

__device__ __forceinline__ void ldm4(uint32_t& r0, uint32_t& r1, uint32_t& r2, uint32_t& r3,
                                     const __half* p) {
    unsigned s = (unsigned)__cvta_generic_to_shared(p);
    asm volatile("ldmatrix.sync.aligned.m8n8.x4.shared.b16 {%0,%1,%2,%3},[%4];\n"
                 : "=r"(r0), "=r"(r1), "=r"(r2), "=r"(r3) : "r"(s));
}
__device__ __forceinline__ void mma16816(float& c0, float& c1, float& c2, float& c3,
                                         uint32_t a0, uint32_t a1, uint32_t a2, uint32_t a3,
                                         uint32_t b0, uint32_t b1) {
    asm volatile("mma.sync.aligned.m16n8k16.row.col.f32.f16.f16.f32 "
                 "{%0,%1,%2,%3},{%4,%5,%6,%7},{%8,%9},{%0,%1,%2,%3};\n"
                 : "+f"(c0), "+f"(c1), "+f"(c2), "+f"(c3)
                 : "r"(a0), "r"(a1), "r"(a2), "r"(a3), "r"(b0), "r"(b1));
}
__device__ __forceinline__ float gelu_tanh(float x) {
    float x3 = x * x * x;
    return 0.5f * x * (1.0f + tanhf(0.7978845608028654f * (x + 0.044715f * x3)));
}

// ---------------------------------------------------------------------------
// Weight transpose + fp32->fp16 convert: W[K][N] -> Wt[N][K]
// ---------------------------------------------------------------------------
__global__ void k_transpose(const float* __restrict__ W, __half* __restrict__ Wt,
                            int K, int N) {
    int i = blockIdx.x * 256 + threadIdx.x;
    if (i >= K * N) return;
    int n = i / K;
    int k = i - n * K;
    Wt[i] = __float2half(W[(size_t)k * N + n]);
}

// ---------------------------------------------------------------------------
// Kernel 1: LN1 + roll(-4,-4) + window partition
// ---------------------------------------------------------------------------
__global__ __launch_bounds__(128) void k_ln1(const float* __restrict__ hs,
                                             const float* __restrict__ g,
                                             const float* __restrict__ b,
                                             __half* __restrict__ xw) {
    int n    = blockIdx.x;
    int bimg = n >> 12;
    int rem  = n & 4095;
    int wid  = rem >> 6, t = rem & 63;
    int wy = wid >> 3, wx = wid & 7;
    int hr = wy * 8 + (t >> 3), wr = wx * 8 + (t & 7);
    int h0 = (hr + SHIFT) & 63, w0 = (wr + SHIFT) & 63;
    size_t src = ((size_t)(bimg << 12) + (h0 << 6) + w0) * CDIM;

    int tid = threadIdx.x;
    float4 v = ((const float4*)(hs + src))[tid];
    float s  = v.x + v.y + v.z + v.w;
    float s2 = v.x * v.x + v.y * v.y + v.z * v.z + v.w * v.w;
#pragma unroll
    for (int o = 16; o; o >>= 1) {
        s  += __shfl_xor_sync(0xffffffffu, s,  o);
        s2 += __shfl_xor_sync(0xffffffffu, s2, o);
    }
    __shared__ float rs[4], rq[4];
    int warp = tid >> 5, lane = tid & 31;
    if (lane == 0) { rs[warp] = s; rq[warp] = s2; }
    __syncthreads();
    s  = rs[0] + rs[1] + rs[2] + rs[3];
    s2 = rq[0] + rq[1] + rq[2] + rq[3];
    float mean = s * (1.0f / 512.0f);
    float var  = s2 * (1.0f / 512.0f) - mean * mean;
    float rstd = rsqrtf(var + 1e-5f);

    int c = tid * 4;
    float4 gv = ((const float4*)g)[tid];
    float4 bv = ((const float4*)b)[tid];
    __half2* o = (__half2*)(xw + (size_t)n * CDIM + c);
    o[0] = __floats2half2_rn((v.x - mean) * rstd * gv.x + bv.x,
                             (v.y - mean) * rstd * gv.y + bv.y);
    o[1] = __floats2half2_rn((v.z - mean) * rstd * gv.z + bv.z,
                             (v.w - mean) * rstd * gv.w + bv.w);
}

// ---------------------------------------------------------------------------
// HMMA GEMM: C[M,N] = A[M,K] fp16 x Bt[N,K]^T fp16, fp32 accum.
// Tile 128x128, BK=64, 3-stage cp.async pipeline, 256 threads, 2 CTAs/SM.
// EPI: 0 +bias->fp16 | 1 +bias->fp32 | 2 gelu(+bias)->fp16 | 3 +bias+res->fp32
// ---------------------------------------------------------------------------
#define BKH   64                  // K halves per stage
#define KW    72                  // padded row width in halves (144 B)
#define ROWB  144                 // row stride bytes
#define STGB  (128 * ROWB)        // 18432 B per operand stage
#define GSM_BIAS 0                // 128 floats
#define GSM_A    1024
#define GSM_B    (GSM_A + 3 * STGB)
#define GSM_TOTAL (GSM_B + 3 * STGB)   // 111616 B

__device__ __forceinline__ void g3_load(char* smem, const __half* A, const __half* Bt,
                                        size_t aBase, size_t bBase, int K,
                                        int st, int ko, int tid) {
    int r  = tid >> 1;
    int s0 = (tid & 1) * 4;
    const __half* ag = A + aBase + (size_t)r * K + ko;
    const __half* bg = Bt + bBase + (size_t)r * K + ko;
    char* pa = smem + GSM_A + st * STGB + r * ROWB;
    char* pb = smem + GSM_B + st * STGB + r * ROWB;
#pragma unroll
    for (int i = 0; i < 4; i++) {
        int sg = s0 + i;
        cp16(pa + sg * 16, ag + sg * 8);
        cp16(pb + sg * 16, bg + sg * 8);
    }
}

template <int EPI>
__global__ __launch_bounds__(256, 2) void gemm16(const __half* __restrict__ A,
                                                 const __half* __restrict__ Bt,
                                                 const float* __restrict__ bias,
                                                 const float* __restrict__ res,
                                                 void* __restrict__ outp,
                                                 int M, int N, int K) {
    extern __shared__ char smem[];
    int tid = threadIdx.x;
    int bx = blockIdx.x, by = blockIdx.y;
    size_t aBase = (size_t)by * 128 * K;
    size_t bBase = (size_t)bx * 128 * K;

    if (tid < 128) ((float*)(smem + GSM_BIAS))[tid] = bias[bx * 128 + tid];

    // prologue: stages 0,1
    g3_load(smem, A, Bt, aBase, bBase, K, 0, 0, tid);
    cp_commit();
    g3_load(smem, A, Bt, aBase, bBase, K, 1, BKH, tid);
    cp_commit();

    int warp = tid >> 5, lane = tid & 31;
    int wm = warp >> 1, wn = warp & 1;          // 4x2 warps; warp tile 32x64

    float acc[2][8][4];
#pragma unroll
    for (int mi = 0; mi < 2; mi++)
#pragma unroll
        for (int ni = 0; ni < 8; ni++)
#pragma unroll
            for (int j = 0; j < 4; j++) acc[mi][ni][j] = 0.0f;

    // ldmatrix base offsets (within a stage)
    int aRow = wm * 32 + (lane & 7) + ((lane >> 3) & 1) * 8;
    int aCol = (lane >> 4) * 8;
    int bRow = wn * 64 + (lane & 7) + (lane >> 4) * 8;
    int bCol = ((lane >> 3) & 1) * 8;

    int niter = K >> 6;
    for (int it = 0; it < niter; ++it) {
        cp_wait1();
        __syncthreads();
        if (it + 2 < niter)
            g3_load(smem, A, Bt, aBase, bBase, K, (it + 2) % 3, (it + 2) << 6, tid);
        cp_commit();

        int st = it % 3;
        const __half* sa = (const __half*)(smem + GSM_A + st * STGB);
        const __half* sb = (const __half*)(smem + GSM_B + st * STGB);
#pragma unroll
        for (int ks = 0; ks < 4; ++ks) {
            uint32_t a[2][4];
#pragma unroll
            for (int mi = 0; mi < 2; mi++)
                ldm4(a[mi][0], a[mi][1], a[mi][2], a[mi][3],
                     sa + (size_t)(aRow + mi * 16) * KW + ks * 16 + aCol);
            uint32_t bf[8][2];
#pragma unroll
            for (int nj = 0; nj < 4; nj++) {
                uint32_t q0, q1, q2, q3;
                ldm4(q0, q1, q2, q3,
                     sb + (size_t)(bRow + nj * 16) * KW + ks * 16 + bCol);
                bf[nj * 2][0] = q0; bf[nj * 2][1] = q1;
                bf[nj * 2 + 1][0] = q2; bf[nj * 2 + 1][1] = q3;
            }
#pragma unroll
            for (int mi = 0; mi < 2; mi++)
#pragma unroll
                for (int ni = 0; ni < 8; ni++)
                    mma16816(acc[mi][ni][0], acc[mi][ni][1], acc[mi][ni][2], acc[mi][ni][3],
                             a[mi][0], a[mi][1], a[mi][2], a[mi][3],
                             bf[ni][0], bf[ni][1]);
        }
    }

    // epilogue
    const float* sbias = (const float*)(smem + GSM_BIAS);
    int gm0 = by * 128 + wm * 32;
    int gn0 = bx * 128 + wn * 64;
    int ln0 = wn * 64;
#pragma unroll
    for (int mi = 0; mi < 2; mi++) {
#pragma unroll
        for (int ni = 0; ni < 8; ni++) {
            int row = gm0 + mi * 16 + (lane >> 2);
            int col = gn0 + ni * 8 + (lane & 3) * 2;
            int lcol = ln0 + ni * 8 + (lane & 3) * 2;
            float bv0 = sbias[lcol], bv1 = sbias[lcol + 1];
#pragma unroll
            for (int hf = 0; hf < 2; hf++) {
                int gr = row + hf * 8;
                float v0 = acc[mi][ni][hf * 2 + 0] + bv0;
                float v1 = acc[mi][ni][hf * 2 + 1] + bv1;
                size_t off = (size_t)gr * N + col;
                if constexpr (EPI == 0) {
                    *(__half2*)((__half*)outp + off) = __floats2half2_rn(v0, v1);
                } else if constexpr (EPI == 1) {
                    *(float2*)((float*)outp + off) = make_float2(v0, v1);
                } else if constexpr (EPI == 2) {
                    *(__half2*)((__half*)outp + off) =
                        __floats2half2_rn(gelu_tanh(v0), gelu_tanh(v1));
                } else {
                    v0 += res[off];
                    v1 += res[off + 1];
                    *(float2*)((float*)outp + off) = make_float2(v0, v1);
                }
            }
        }
    }
}

// ---------------------------------------------------------------------------
// Kernel 3: attention. One block per (window, head). 128 threads.
// ---------------------------------------------------------------------------
__global__ __launch_bounds__(128) void k_attn(const __half* __restrict__ qkv,
                                              __half* __restrict__ attn) {
    __shared__ float sq[64][36];
    __shared__ float sk[64][36];
    __shared__ float sv[64][36];
    __shared__ float sp[64][65];
    __shared__ float sinv[64];
    __shared__ int   sid[64];

    int blk = blockIdx.x;
    int w = blk >> 4, h = blk & 15;
    int tid = threadIdx.x;

    const __half* base = qkv + (size_t)w * SEQ * (3 * CDIM) + h * HEADD;
    for (int i = tid; i < SEQ * HEADD; i += 128) {
        int r = i >> 5, d = i & 31;
        const __half* p = base + (size_t)r * (3 * CDIM) + d;
        sq[r][d] = __half2float(p[0])    * 0.17677669529663687f;
        sk[r][d] = __half2float(p[512]);
        sv[r][d] = __half2float(p[1024]);
    }
    if (tid < 64) {
        int wim = w & 63;
        int wy = wim >> 3, wx = wim & 7;
        int hh = wy * 8 + (tid >> 3), ww = wx * 8 + (tid & 7);
        int rh = (hh < 56) ? 0 : ((hh < 60) ? 1 : 2);
        int rw = (ww < 56) ? 0 : ((ww < 60) ? 1 : 2);
        sid[tid] = rh * 3 + rw;
    }
    __syncthreads();

    {
        int qr = tid >> 1, k0 = (tid & 1) * 32;
        float4 q4[8];
#pragma unroll
        for (int i = 0; i < 8; i++) q4[i] = ((const float4*)sq[qr])[i];
        int myid = sid[qr];
        for (int kk = 0; kk < 32; kk++) {
            int kr = k0 + kk;
            float s;
            if (sid[kr] != myid) {
                s = -10000.0f;
            } else {
                const float4* kp = (const float4*)sk[kr];
                s = 0.0f;
#pragma unroll
                for (int i = 0; i < 8; i++) {
                    float4 kv = kp[i];
                    s += q4[i].x * kv.x + q4[i].y * kv.y + q4[i].z * kv.z + q4[i].w * kv.w;
                }
            }
            sp[qr][kr] = s;
        }
    }
    __syncthreads();

    if (tid < 64) {
        float mx = -1e30f;
#pragma unroll 8
        for (int k = 0; k < 64; k++) mx = fmaxf(mx, sp[tid][k]);
        float sum = 0.0f;
#pragma unroll 8
        for (int k = 0; k < 64; k++) {
            float e = __expf(sp[tid][k] - mx);
            sp[tid][k] = e;
            sum += e;
        }
        sinv[tid] = 1.0f / sum;
    }
    __syncthreads();

    {
        int r = tid >> 1, d0 = (tid & 1) * 16;
        float acc[16];
#pragma unroll
        for (int j = 0; j < 16; j++) acc[j] = 0.0f;
        for (int k = 0; k < 64; k++) {
            float p = sp[r][k];
            const float4* vp = (const float4*)&sv[k][d0];
#pragma unroll
            for (int j4 = 0; j4 < 4; j4++) {
                float4 vv = vp[j4];
                acc[j4 * 4 + 0] += p * vv.x;
                acc[j4 * 4 + 1] += p * vv.y;
                acc[j4 * 4 + 2] += p * vv.z;
                acc[j4 * 4 + 3] += p * vv.w;
            }
        }
        float inv = sinv[r];
        __half2* o = (__half2*)(attn + (size_t)(w * SEQ + r) * CDIM + h * HEADD + d0);
#pragma unroll
        for (int j = 0; j < 8; j++)
            o[j] = __floats2half2_rn(acc[2 * j] * inv, acc[2 * j + 1] * inv);
    }
}

// ---------------------------------------------------------------------------
// Kernel 5: window reverse + roll(+4,+4) + residual + LN2
// ---------------------------------------------------------------------------
__global__ __launch_bounds__(128) void k_rev_ln2(const float* __restrict__ hs,
                                                 const float* __restrict__ proj,
                                                 const float* __restrict__ g,
                                                 const float* __restrict__ b,
                                                 float* __restrict__ x,
                                                 __half* __restrict__ hout) {
    int m = blockIdx.x;
    int bimg = m >> 12;
    int hw = m & 4095;
    int h0 = hw >> 6, w0 = hw & 63;
    int hr = (h0 + 64 - SHIFT) & 63, wr = (w0 + 64 - SHIFT) & 63;
    int wy = hr >> 3, rr = hr & 7, wx = wr >> 3, cc = wr & 7;
    int n = (bimg << 12) + ((wy * 8 + wx) << 6) + (rr * 8 + cc);

    int tid = threadIdx.x;
    float4 a = ((const float4*)(hs + (size_t)m * CDIM))[tid];
    float4 p = ((const float4*)(proj + (size_t)n * CDIM))[tid];
    float4 v = make_float4(a.x + p.x, a.y + p.y, a.z + p.z, a.w + p.w);
    ((float4*)(x + (size_t)m * CDIM))[tid] = v;

    float s  = v.x + v.y + v.z + v.w;
    float s2 = v.x * v.x + v.y * v.y + v.z * v.z + v.w * v.w;
#pragma unroll
    for (int o = 16; o; o >>= 1) {
        s  += __shfl_xor_sync(0xffffffffu, s,  o);
        s2 += __shfl_xor_sync(0xffffffffu, s2, o);
    }
    __shared__ float rs[4], rq[4];
    int warp = tid >> 5, lane = tid & 31;
    if (lane == 0) { rs[warp] = s; rq[warp] = s2; }
    __syncthreads();
    s  = rs[0] + rs[1] + rs[2] + rs[3];
    s2 = rq[0] + rq[1] + rq[2] + rq[3];
    float mean = s * (1.0f / 512.0f);
    float var  = s2 * (1.0f / 512.0f) - mean * mean;
    float rstd = rsqrtf(var + 1e-5f);

    int c = tid * 4;
    float4 gv = ((const float4*)g)[tid];
    float4 bv = ((const float4*)b)[tid];
    __half2* o = (__half2*)(hout + (size_t)m * CDIM + c);
    o[0] = __floats2half2_rn((v.x - mean) * rstd * gv.x + bv.x,
                             (v.y - mean) * rstd * gv.y + bv.y);
    o[1] = __floats2half2_rn((v.z - mean) * rstd * gv.z + bv.z,
                             (v.w - mean) * rstd * gv.w + bv.w);
}

// ---------------------------------------------------------------------------
// Host launcher
// ---------------------------------------------------------------------------
extern "C" void kernel_launch(void* const* d_in, const int* in_sizes, int n_in,
                              void* d_out, int out_size) {
    const float* hs   = (const float*)d_in[0];
    const float* Wqkv = (const float*)d_in[1];
    const float* bqkv = (const float*)d_in[2];
    const float* Wo   = (const float*)d_in[3];
    const float* bo   = (const float*)d_in[4];
    const float* ln1g = (const float*)d_in[5];
    const float* ln1b = (const float*)d_in[6];
    const float* ln2g = (const float*)d_in[7];
    const float* ln2b = (const float*)d_in[8];
    const float* W1   = (const float*)d_in[9];
    const float* b1   = (const float*)d_in[10];
    const float* W2   = (const float*)d_in[11];
    const float* b2   = (const float*)d_in[12];

    __half *xw, *qkv, *attn, *hbuf, *ff, *wqkvT, *woT, *w1T, *w2T;
    float *proj, *xbuf;
    cudaGetSymbolAddress((void**)&xw,    g_xw);
    cudaGetSymbolAddress((void**)&qkv,   g_qkv);
    cudaGetSymbolAddress((void**)&attn,  g_attn);
    cudaGetSymbolAddress((void**)&proj,  g_proj);
    cudaGetSymbolAddress((void**)&xbuf,  g_x);
    cudaGetSymbolAddress((void**)&hbuf,  g_h);
    cudaGetSymbolAddress((void**)&ff,    g_ff);
    cudaGetSymbolAddress((void**)&wqkvT, g_wqkvT);
    cudaGetSymbolAddress((void**)&woT,   g_woT);
    cudaGetSymbolAddress((void**)&w1T,   g_w1T);
    cudaGetSymbolAddress((void**)&w2T,   g_w2T);

    cudaFuncSetAttribute(gemm16<0>, cudaFuncAttributeMaxDynamicSharedMemorySize, GSM_TOTAL);
    cudaFuncSetAttribute(gemm16<1>, cudaFuncAttributeMaxDynamicSharedMemorySize, GSM_TOTAL);
    cudaFuncSetAttribute(gemm16<2>, cudaFuncAttributeMaxDynamicSharedMemorySize, GSM_TOTAL);
    cudaFuncSetAttribute(gemm16<3>, cudaFuncAttributeMaxDynamicSharedMemorySize, GSM_TOTAL);

    // weight transposes (fp32 -> fp16, [K,N] -> [N,K])
    k_transpose<<<(512 * 1536 + 255) / 256, 256>>>(Wqkv, wqkvT, 512, 1536);
    k_transpose<<<(512 * 512  + 255) / 256, 256>>>(Wo,   woT,   512, 512);
    k_transpose<<<(512 * 2048 + 255) / 256, 256>>>(W1,   w1T,   512, 2048);
    k_transpose<<<(2048 * 512 + 255) / 256, 256>>>(W2,   w2T,   2048, 512);

    // 1. LN1 + shift + partition
    k_ln1<<<MTOK, 128>>>(hs, ln1g, ln1b, xw);

    // 2. QKV GEMM: [131072,512] x [512,1536] -> fp16
    gemm16<0><<<dim3(1536 / 128, MTOK / 128), 256, GSM_TOTAL>>>(
        xw, wqkvT, bqkv, nullptr, qkv, MTOK, 1536, 512);

    // 3. attention
    k_attn<<<2048 * NHEAD, 128>>>(qkv, attn);

    // 4. out projection: [131072,512] x [512,512] -> fp32
    gemm16<1><<<dim3(512 / 128, MTOK / 128), 256, GSM_TOTAL>>>(
        attn, woT, bo, nullptr, proj, MTOK, 512, 512);

    // 5. reverse + residual + LN2
    k_rev_ln2<<<MTOK, 128>>>(hs, proj, ln2g, ln2b, xbuf, hbuf);

    // 6. MLP up + gelu: [131072,512] x [512,2048] -> fp16
    gemm16<2><<<dim3(2048 / 128, MTOK / 128), 256, GSM_TOTAL>>>(
        hbuf, w1T, b1, nullptr, ff, MTOK, 2048, 512);

    // 7. MLP down + residual: [131072,2048] x [2048,512] -> fp32 d_out
    gemm16<3><<<dim3(512 / 128, MTOK / 128), 256, GSM_TOTAL>>>(
        ff, w2T, b2, xbuf, d_out, MTOK, 512, 2048);
}

// round 4
// speedup vs baseline: 1.1860x; 1.1860x over previous
#include <cuda_runtime.h>
#include <cuda_fp16.h>
#include <cstdint>

// ---------------------------------------------------------------------------
// Problem constants
// ---------------------------------------------------------------------------
#define BATCH 32
#define CDIM  512
#define NHEAD 16
#define SHIFT 4
#define SEQ   64
#define HEADD 32
#define FFDIM 2048
#define MTOK  131072

// ---------------------------------------------------------------------------
// Scratch
// ---------------------------------------------------------------------------
__device__ __half g_xw  [ (size_t)MTOK * CDIM  ];
__device__ __half g_qkv [ (size_t)MTOK * 3*CDIM];
__device__ __half g_attn[ (size_t)MTOK * CDIM  ];
__device__ float  g_proj[ (size_t)MTOK * CDIM  ];
__device__ float  g_x   [ (size_t)MTOK * CDIM  ];
__device__ __half g_h   [ (size_t)MTOK * CDIM  ];
__device__ __half g_ff  [ (size_t)MTOK * FFDIM ];
__device__ __half g_wqkvT[3*CDIM * CDIM];
__device__ __half g_woT  [CDIM * CDIM];
__device__ __half g_w1T  [FFDIM * CDIM];
__device__ __half g_w2T  [CDIM * FFDIM];

// ---------------------------------------------------------------------------
// Helpers
// ---------------------------------------------------------------------------
__device__ __forceinline__ void cp16(void* smem, const void* gmem) {
    unsigned s = (unsigned)__cvta_generic_to_shared(smem);
    asm volatile("cp.async.cg.shared.global [%0], [%1], 16;\n" :: "r"(s), "l"(gmem));
}
__device__ __forceinline__ void cp_commit() { asm volatile("cp.async.commit_group;\n"); }
__device__ __forceinline__ void cp_wait2()  { asm volatile("cp.async.wait_group 2;\n"); }

__device__ __forceinline__ void ldm4(uint32_t& r0, uint32_t& r1, uint32_t& r2, uint32_t& r3,
                                     const __half* p) {
    unsigned s = (unsigned)__cvta_generic_to_shared(p);
    asm volatile("ldmatrix.sync.aligned.m8n8.x4.shared.b16 {%0,%1,%2,%3},[%4];\n"
                 : "=r"(r0), "=r"(r1), "=r"(r2), "=r"(r3) : "r"(s));
}
__device__ __forceinline__ void mma16816(float& c0, float& c1, float& c2, float& c3,
                                         uint32_t a0, uint32_t a1, uint32_t a2, uint32_t a3,
                                         uint32_t b0, uint32_t b1) {
    asm volatile("mma.sync.aligned.m16n8k16.row.col.f32.f16.f16.f32 "
                 "{%0,%1,%2,%3},{%4,%5,%6,%7},{%8,%9},{%0,%1,%2,%3};\n"
                 : "+f"(c0), "+f"(c1), "+f"(c2), "+f"(c3)
                 : "r"(a0), "r"(a1), "r"(a2), "r"(a3), "r"(b0), "r"(b1));
}
__device__ __forceinline__ float gelu_tanh(float x) {
    float x3 = x * x * x;
    return 0.5f * x * (1.0f + tanhf(0.7978845608028654f * (x + 0.044715f * x3)));
}

// ---------------------------------------------------------------------------
// Weight transpose + fp32->fp16 convert: W[K][N] -> Wt[N][K]
// ---------------------------------------------------------------------------
__global__ void k_transpose(const float* __restrict__ W, __half* __restrict__ Wt,
                            int K, int N) {
    int i = blockIdx.x * 256 + threadIdx.x;
    if (i >= K * N) return;
    int n = i / K;
    int k = i - n * K;
    Wt[i] = __float2half(W[(size_t)k * N + n]);
}

// ---------------------------------------------------------------------------
// Kernel 1: LN1 + roll(-4,-4) + window partition
// ---------------------------------------------------------------------------
__global__ __launch_bounds__(128) void k_ln1(const float* __restrict__ hs,
                                             const float* __restrict__ g,
                                             const float* __restrict__ b,
                                             __half* __restrict__ xw) {
    int n    = blockIdx.x;
    int bimg = n >> 12;
    int rem  = n & 4095;
    int wid  = rem >> 6, t = rem & 63;
    int wy = wid >> 3, wx = wid & 7;
    int hr = wy * 8 + (t >> 3), wr = wx * 8 + (t & 7);
    int h0 = (hr + SHIFT) & 63, w0 = (wr + SHIFT) & 63;
    size_t src = ((size_t)(bimg << 12) + (h0 << 6) + w0) * CDIM;

    int tid = threadIdx.x;
    float4 v = ((const float4*)(hs + src))[tid];
    float s  = v.x + v.y + v.z + v.w;
    float s2 = v.x * v.x + v.y * v.y + v.z * v.z + v.w * v.w;
#pragma unroll
    for (int o = 16; o; o >>= 1) {
        s  += __shfl_xor_sync(0xffffffffu, s,  o);
        s2 += __shfl_xor_sync(0xffffffffu, s2, o);
    }
    __shared__ float rs[4], rq[4];
    int warp = tid >> 5, lane = tid & 31;
    if (lane == 0) { rs[warp] = s; rq[warp] = s2; }
    __syncthreads();
    s  = rs[0] + rs[1] + rs[2] + rs[3];
    s2 = rq[0] + rq[1] + rq[2] + rq[3];
    float mean = s * (1.0f / 512.0f);
    float var  = s2 * (1.0f / 512.0f) - mean * mean;
    float rstd = rsqrtf(var + 1e-5f);

    int c = tid * 4;
    float4 gv = ((const float4*)g)[tid];
    float4 bv = ((const float4*)b)[tid];
    __half2* o = (__half2*)(xw + (size_t)n * CDIM + c);
    o[0] = __floats2half2_rn((v.x - mean) * rstd * gv.x + bv.x,
                             (v.y - mean) * rstd * gv.y + bv.y);
    o[1] = __floats2half2_rn((v.z - mean) * rstd * gv.z + bv.z,
                             (v.w - mean) * rstd * gv.w + bv.w);
}

// ---------------------------------------------------------------------------
// HMMA GEMM: C[M,N] = A[M,K] fp16 x Bt[N,K]^T fp16, fp32 accum.
// Tile 128x128, BK=32, 4-stage cp.async ring (2 groups in flight), 256 thr,
// 2 CTAs/SM. EPI: 0 +bias->fp16 | 1 +bias->fp32 | 2 gelu->fp16 | 3 +res->fp32
// ---------------------------------------------------------------------------
#define KW    40                  // padded row width in halves (80 B)
#define ROWB  80
#define STGB  (128 * ROWB)        // 10240 B per operand stage
#define NSTG  4
#define GSM_BIAS 0
#define GSM_A    1024
#define GSM_B    (GSM_A + NSTG * STGB)       // 41984
#define GSM_TOTAL (GSM_B + NSTG * STGB)      // 82944 B

__device__ __forceinline__ void g4_load(char* smem, const __half* A, const __half* Bt,
                                        size_t aBase, size_t bBase, int K,
                                        int st, int ko, int tid) {
    // per operand per stage: 128 rows x 64 B = 512 chunks of 16B; 2 per thread
    char* pa = smem + GSM_A + st * STGB;
    char* pb = smem + GSM_B + st * STGB;
#pragma unroll
    for (int j = 0; j < 2; j++) {
        int c = tid + 256 * j;
        int r = c >> 2, sg = c & 3;
        cp16(pa + r * ROWB + sg * 16, A + aBase + (size_t)r * K + ko + sg * 8);
        cp16(pb + r * ROWB + sg * 16, Bt + bBase + (size_t)r * K + ko + sg * 8);
    }
}

template <int EPI>
__global__ __launch_bounds__(256, 2) void gemm16(const __half* __restrict__ A,
                                                 const __half* __restrict__ Bt,
                                                 const float* __restrict__ bias,
                                                 const float* __restrict__ res,
                                                 void* __restrict__ outp,
                                                 int M, int N, int K) {
    extern __shared__ char smem[];
    int tid = threadIdx.x;
    int bx = blockIdx.x, by = blockIdx.y;
    size_t aBase = (size_t)by * 128 * K;
    size_t bBase = (size_t)bx * 128 * K;

    if (tid < 128) ((float*)(smem + GSM_BIAS))[tid] = bias[bx * 128 + tid];

    int niter = K >> 5;           // BK=32; K>=512 so niter>=16

    // prologue: stages 0,1,2 (three groups)
#pragma unroll
    for (int st = 0; st < 3; st++) {
        g4_load(smem, A, Bt, aBase, bBase, K, st, st << 5, tid);
        cp_commit();
    }

    int warp = tid >> 5, lane = tid & 31;
    int wm = warp >> 1, wn = warp & 1;          // 4x2 warps; warp tile 32x64

    float acc[2][8][4];
#pragma unroll
    for (int mi = 0; mi < 2; mi++)
#pragma unroll
        for (int ni = 0; ni < 8; ni++)
#pragma unroll
            for (int j = 0; j < 4; j++) acc[mi][ni][j] = 0.0f;

    int aRow = wm * 32 + (lane & 7) + ((lane >> 3) & 1) * 8;
    int aCol = (lane >> 4) * 8;
    int bRow = wn * 64 + (lane & 7) + (lane >> 4) * 8;
    int bCol = ((lane >> 3) & 1) * 8;

    for (int it = 0; it < niter; ++it) {
        cp_wait2();               // newest 2 groups (stages it+1, it+2) may be pending
        __syncthreads();
        if (it + 3 < niter)
            g4_load(smem, A, Bt, aBase, bBase, K, (it + 3) & 3, (it + 3) << 5, tid);
        cp_commit();              // always commit (empty group at tail keeps invariant)

        int st = it & 3;
        const __half* sa = (const __half*)(smem + GSM_A + st * STGB);
        const __half* sb = (const __half*)(smem + GSM_B + st * STGB);
#pragma unroll
        for (int ks = 0; ks < 2; ++ks) {
            uint32_t a[2][4];
#pragma unroll
            for (int mi = 0; mi < 2; mi++)
                ldm4(a[mi][0], a[mi][1], a[mi][2], a[mi][3],
                     sa + (size_t)(aRow + mi * 16) * KW + ks * 16 + aCol);
            uint32_t bf[8][2];
#pragma unroll
            for (int nj = 0; nj < 4; nj++) {
                uint32_t q0, q1, q2, q3;
                ldm4(q0, q1, q2, q3,
                     sb + (size_t)(bRow + nj * 16) * KW + ks * 16 + bCol);
                bf[nj * 2][0] = q0; bf[nj * 2][1] = q1;
                bf[nj * 2 + 1][0] = q2; bf[nj * 2 + 1][1] = q3;
            }
#pragma unroll
            for (int mi = 0; mi < 2; mi++)
#pragma unroll
                for (int ni = 0; ni < 8; ni++)
                    mma16816(acc[mi][ni][0], acc[mi][ni][1], acc[mi][ni][2], acc[mi][ni][3],
                             a[mi][0], a[mi][1], a[mi][2], a[mi][3],
                             bf[ni][0], bf[ni][1]);
        }
    }

    // epilogue
    const float* sbias = (const float*)(smem + GSM_BIAS);
    int gm0 = by * 128 + wm * 32;
    int gn0 = bx * 128 + wn * 64;
    int ln0 = wn * 64;
#pragma unroll
    for (int mi = 0; mi < 2; mi++) {
#pragma unroll
        for (int ni = 0; ni < 8; ni++) {
            int row = gm0 + mi * 16 + (lane >> 2);
            int col = gn0 + ni * 8 + (lane & 3) * 2;
            int lcol = ln0 + ni * 8 + (lane & 3) * 2;
            float bv0 = sbias[lcol], bv1 = sbias[lcol + 1];
#pragma unroll
            for (int hf = 0; hf < 2; hf++) {
                int gr = row + hf * 8;
                float v0 = acc[mi][ni][hf * 2 + 0] + bv0;
                float v1 = acc[mi][ni][hf * 2 + 1] + bv1;
                size_t off = (size_t)gr * N + col;
                if constexpr (EPI == 0) {
                    *(__half2*)((__half*)outp + off) = __floats2half2_rn(v0, v1);
                } else if constexpr (EPI == 1) {
                    *(float2*)((float*)outp + off) = make_float2(v0, v1);
                } else if constexpr (EPI == 2) {
                    *(__half2*)((__half*)outp + off) =
                        __floats2half2_rn(gelu_tanh(v0), gelu_tanh(v1));
                } else {
                    v0 += res[off];
                    v1 += res[off + 1];
                    *(float2*)((float*)outp + off) = make_float2(v0, v1);
                }
            }
        }
    }
}

// ---------------------------------------------------------------------------
// Kernel 3: attention. One block per (window, head). 128 threads.
// ---------------------------------------------------------------------------
__global__ __launch_bounds__(128) void k_attn(const __half* __restrict__ qkv,
                                              __half* __restrict__ attn) {
    __shared__ float sq[64][36];
    __shared__ float sk[64][36];
    __shared__ float sv[64][36];
    __shared__ float sp[64][65];
    __shared__ float sinv[64];
    __shared__ int   sid[64];

    int blk = blockIdx.x;
    int w = blk >> 4, h = blk & 15;
    int tid = threadIdx.x;

    const __half* base = qkv + (size_t)w * SEQ * (3 * CDIM) + h * HEADD;
    for (int i = tid; i < SEQ * HEADD; i += 128) {
        int r = i >> 5, d = i & 31;
        const __half* p = base + (size_t)r * (3 * CDIM) + d;
        sq[r][d] = __half2float(p[0])    * 0.17677669529663687f;
        sk[r][d] = __half2float(p[512]);
        sv[r][d] = __half2float(p[1024]);
    }
    if (tid < 64) {
        int wim = w & 63;
        int wy = wim >> 3, wx = wim & 7;
        int hh = wy * 8 + (tid >> 3), ww = wx * 8 + (tid & 7);
        int rh = (hh < 56) ? 0 : ((hh < 60) ? 1 : 2);
        int rw = (ww < 56) ? 0 : ((ww < 60) ? 1 : 2);
        sid[tid] = rh * 3 + rw;
    }
    __syncthreads();

    {
        int qr = tid >> 1, k0 = (tid & 1) * 32;
        float4 q4[8];
#pragma unroll
        for (int i = 0; i < 8; i++) q4[i] = ((const float4*)sq[qr])[i];
        int myid = sid[qr];
        for (int kk = 0; kk < 32; kk++) {
            int kr = k0 + kk;
            float s;
            if (sid[kr] != myid) {
                s = -10000.0f;
            } else {
                const float4* kp = (const float4*)sk[kr];
                s = 0.0f;
#pragma unroll
                for (int i = 0; i < 8; i++) {
                    float4 kv = kp[i];
                    s += q4[i].x * kv.x + q4[i].y * kv.y + q4[i].z * kv.z + q4[i].w * kv.w;
                }
            }
            sp[qr][kr] = s;
        }
    }
    __syncthreads();

    if (tid < 64) {
        float mx = -1e30f;
#pragma unroll 8
        for (int k = 0; k < 64; k++) mx = fmaxf(mx, sp[tid][k]);
        float sum = 0.0f;
#pragma unroll 8
        for (int k = 0; k < 64; k++) {
            float e = __expf(sp[tid][k] - mx);
            sp[tid][k] = e;
            sum += e;
        }
        sinv[tid] = 1.0f / sum;
    }
    __syncthreads();

    {
        int r = tid >> 1, d0 = (tid & 1) * 16;
        float acc[16];
#pragma unroll
        for (int j = 0; j < 16; j++) acc[j] = 0.0f;
        for (int k = 0; k < 64; k++) {
            float p = sp[r][k];
            const float4* vp = (const float4*)&sv[k][d0];
#pragma unroll
            for (int j4 = 0; j4 < 4; j4++) {
                float4 vv = vp[j4];
                acc[j4 * 4 + 0] += p * vv.x;
                acc[j4 * 4 + 1] += p * vv.y;
                acc[j4 * 4 + 2] += p * vv.z;
                acc[j4 * 4 + 3] += p * vv.w;
            }
        }
        float inv = sinv[r];
        __half2* o = (__half2*)(attn + (size_t)(w * SEQ + r) * CDIM + h * HEADD + d0);
#pragma unroll
        for (int j = 0; j < 8; j++)
            o[j] = __floats2half2_rn(acc[2 * j] * inv, acc[2 * j + 1] * inv);
    }
}

// ---------------------------------------------------------------------------
// Kernel 5: window reverse + roll(+4,+4) + residual + LN2
// ---------------------------------------------------------------------------
__global__ __launch_bounds__(128) void k_rev_ln2(const float* __restrict__ hs,
                                                 const float* __restrict__ proj,
                                                 const float* __restrict__ g,
                                                 const float* __restrict__ b,
                                                 float* __restrict__ x,
                                                 __half* __restrict__ hout) {
    int m = blockIdx.x;
    int bimg = m >> 12;
    int hw = m & 4095;
    int h0 = hw >> 6, w0 = hw & 63;
    int hr = (h0 + 64 - SHIFT) & 63, wr = (w0 + 64 - SHIFT) & 63;
    int wy = hr >> 3, rr = hr & 7, wx = wr >> 3, cc = wr & 7;
    int n = (bimg << 12) + ((wy * 8 + wx) << 6) + (rr * 8 + cc);

    int tid = threadIdx.x;
    float4 a = ((const float4*)(hs + (size_t)m * CDIM))[tid];
    float4 p = ((const float4*)(proj + (size_t)n * CDIM))[tid];
    float4 v = make_float4(a.x + p.x, a.y + p.y, a.z + p.z, a.w + p.w);
    ((float4*)(x + (size_t)m * CDIM))[tid] = v;

    float s  = v.x + v.y + v.z + v.w;
    float s2 = v.x * v.x + v.y * v.y + v.z * v.z + v.w * v.w;
#pragma unroll
    for (int o = 16; o; o >>= 1) {
        s  += __shfl_xor_sync(0xffffffffu, s,  o);
        s2 += __shfl_xor_sync(0xffffffffu, s2, o);
    }
    __shared__ float rs[4], rq[4];
    int warp = tid >> 5, lane = tid & 31;
    if (lane == 0) { rs[warp] = s; rq[warp] = s2; }
    __syncthreads();
    s  = rs[0] + rs[1] + rs[2] + rs[3];
    s2 = rq[0] + rq[1] + rq[2] + rq[3];
    float mean = s * (1.0f / 512.0f);
    float var  = s2 * (1.0f / 512.0f) - mean * mean;
    float rstd = rsqrtf(var + 1e-5f);

    int c = tid * 4;
    float4 gv = ((const float4*)g)[tid];
    float4 bv = ((const float4*)b)[tid];
    __half2* o = (__half2*)(hout + (size_t)m * CDIM + c);
    o[0] = __floats2half2_rn((v.x - mean) * rstd * gv.x + bv.x,
                             (v.y - mean) * rstd * gv.y + bv.y);
    o[1] = __floats2half2_rn((v.z - mean) * rstd * gv.z + bv.z,
                             (v.w - mean) * rstd * gv.w + bv.w);
}

// ---------------------------------------------------------------------------
// Host launcher
// ---------------------------------------------------------------------------
extern "C" void kernel_launch(void* const* d_in, const int* in_sizes, int n_in,
                              void* d_out, int out_size) {
    const float* hs   = (const float*)d_in[0];
    const float* Wqkv = (const float*)d_in[1];
    const float* bqkv = (const float*)d_in[2];
    const float* Wo   = (const float*)d_in[3];
    const float* bo   = (const float*)d_in[4];
    const float* ln1g = (const float*)d_in[5];
    const float* ln1b = (const float*)d_in[6];
    const float* ln2g = (const float*)d_in[7];
    const float* ln2b = (const float*)d_in[8];
    const float* W1   = (const float*)d_in[9];
    const float* b1   = (const float*)d_in[10];
    const float* W2   = (const float*)d_in[11];
    const float* b2   = (const float*)d_in[12];

    __half *xw, *qkv, *attn, *hbuf, *ff, *wqkvT, *woT, *w1T, *w2T;
    float *proj, *xbuf;
    cudaGetSymbolAddress((void**)&xw,    g_xw);
    cudaGetSymbolAddress((void**)&qkv,   g_qkv);
    cudaGetSymbolAddress((void**)&attn,  g_attn);
    cudaGetSymbolAddress((void**)&proj,  g_proj);
    cudaGetSymbolAddress((void**)&xbuf,  g_x);
    cudaGetSymbolAddress((void**)&hbuf,  g_h);
    cudaGetSymbolAddress((void**)&ff,    g_ff);
    cudaGetSymbolAddress((void**)&wqkvT, g_wqkvT);
    cudaGetSymbolAddress((void**)&woT,   g_woT);
    cudaGetSymbolAddress((void**)&w1T,   g_w1T);
    cudaGetSymbolAddress((void**)&w2T,   g_w2T);

    cudaFuncSetAttribute(gemm16<0>, cudaFuncAttributeMaxDynamicSharedMemorySize, GSM_TOTAL);
    cudaFuncSetAttribute(gemm16<1>, cudaFuncAttributeMaxDynamicSharedMemorySize, GSM_TOTAL);
    cudaFuncSetAttribute(gemm16<2>, cudaFuncAttributeMaxDynamicSharedMemorySize, GSM_TOTAL);
    cudaFuncSetAttribute(gemm16<3>, cudaFuncAttributeMaxDynamicSharedMemorySize, GSM_TOTAL);

    // weight transposes (fp32 -> fp16, [K,N] -> [N,K])
    k_transpose<<<(512 * 1536 + 255) / 256, 256>>>(Wqkv, wqkvT, 512, 1536);
    k_transpose<<<(512 * 512  + 255) / 256, 256>>>(Wo,   woT,   512, 512);
    k_transpose<<<(512 * 2048 + 255) / 256, 256>>>(W1,   w1T,   512, 2048);
    k_transpose<<<(2048 * 512 + 255) / 256, 256>>>(W2,   w2T,   2048, 512);

    // 1. LN1 + shift + partition
    k_ln1<<<MTOK, 128>>>(hs, ln1g, ln1b, xw);

    // 2. QKV GEMM: [131072,512] x [512,1536] -> fp16
    gemm16<0><<<dim3(1536 / 128, MTOK / 128), 256, GSM_TOTAL>>>(
        xw, wqkvT, bqkv, nullptr, qkv, MTOK, 1536, 512);

    // 3. attention
    k_attn<<<2048 * NHEAD, 128>>>(qkv, attn);

    // 4. out projection: [131072,512] x [512,512] -> fp32
    gemm16<1><<<dim3(512 / 128, MTOK / 128), 256, GSM_TOTAL>>>(
        attn, woT, bo, nullptr, proj, MTOK, 512, 512);

    // 5. reverse + residual + LN2
    k_rev_ln2<<<MTOK, 128>>>(hs, proj, ln2g, ln2b, xbuf, hbuf);

    // 6. MLP up + gelu: [131072,512] x [512,2048] -> fp16
    gemm16<2><<<dim3(2048 / 128, MTOK / 128), 256, GSM_TOTAL>>>(
        hbuf, w1T, b1, nullptr, ff, MTOK, 2048, 512);

    // 7. MLP down + residual: [131072,2048] x [2048,512] -> fp32 d_out
    gemm16<3><<<dim3(512 / 128, MTOK / 128), 256, GSM_TOTAL>>>(
        ff, w2T, b2, xbuf, d_out, MTOK, 512, 2048);
}

// round 5
// speedup vs baseline: 1.4879x; 1.2546x over previous
#include <cuda_runtime.h>
#include <cuda_fp16.h>
#include <cstdint>

// ---------------------------------------------------------------------------
// Problem constants
// ---------------------------------------------------------------------------
#define BATCH 32
#define CDIM  512
#define NHEAD 16
#define SHIFT 4
#define SEQ   64
#define HEADD 32
#define FFDIM 2048
#define MTOK  131072

// ---------------------------------------------------------------------------
// Scratch
// ---------------------------------------------------------------------------
__device__ __half g_xw  [ (size_t)MTOK * CDIM  ];
__device__ __half g_qkv [ (size_t)MTOK * 3*CDIM];
__device__ __half g_attn[ (size_t)MTOK * CDIM  ];
__device__ float  g_proj[ (size_t)MTOK * CDIM  ];
__device__ float  g_x   [ (size_t)MTOK * CDIM  ];
__device__ __half g_h   [ (size_t)MTOK * CDIM  ];
__device__ __half g_ff  [ (size_t)MTOK * FFDIM ];
__device__ __half g_wqkvT[3*CDIM * CDIM];
__device__ __half g_woT  [CDIM * CDIM];
__device__ __half g_w1T  [FFDIM * CDIM];
__device__ __half g_w2T  [CDIM * FFDIM];

// ---------------------------------------------------------------------------
// Helpers
// ---------------------------------------------------------------------------
__device__ __forceinline__ void cp16(void* smem, const void* gmem) {
    unsigned s = (unsigned)__cvta_generic_to_shared(smem);
    asm volatile("cp.async.cg.shared.global [%0], [%1], 16;\n" :: "r"(s), "l"(gmem));
}
__device__ __forceinline__ void cp_commit() { asm volatile("cp.async.commit_group;\n"); }
__device__ __forceinline__ void cp_wait2()  { asm volatile("cp.async.wait_group 2;\n"); }
__device__ __forceinline__ void cp_wait0()  { asm volatile("cp.async.wait_group 0;\n"); }

__device__ __forceinline__ void ldm4(uint32_t& r0, uint32_t& r1, uint32_t& r2, uint32_t& r3,
                                     const __half* p) {
    unsigned s = (unsigned)__cvta_generic_to_shared(p);
    asm volatile("ldmatrix.sync.aligned.m8n8.x4.shared.b16 {%0,%1,%2,%3},[%4];\n"
                 : "=r"(r0), "=r"(r1), "=r"(r2), "=r"(r3) : "r"(s));
}
__device__ __forceinline__ void ldm4t(uint32_t& r0, uint32_t& r1, uint32_t& r2, uint32_t& r3,
                                      const __half* p) {
    unsigned s = (unsigned)__cvta_generic_to_shared(p);
    asm volatile("ldmatrix.sync.aligned.m8n8.x4.trans.shared.b16 {%0,%1,%2,%3},[%4];\n"
                 : "=r"(r0), "=r"(r1), "=r"(r2), "=r"(r3) : "r"(s));
}
__device__ __forceinline__ void mma16816(float& c0, float& c1, float& c2, float& c3,
                                         uint32_t a0, uint32_t a1, uint32_t a2, uint32_t a3,
                                         uint32_t b0, uint32_t b1) {
    asm volatile("mma.sync.aligned.m16n8k16.row.col.f32.f16.f16.f32 "
                 "{%0,%1,%2,%3},{%4,%5,%6,%7},{%8,%9},{%0,%1,%2,%3};\n"
                 : "+f"(c0), "+f"(c1), "+f"(c2), "+f"(c3)
                 : "r"(a0), "r"(a1), "r"(a2), "r"(a3), "r"(b0), "r"(b1));
}
__device__ __forceinline__ float gelu_tanh(float x) {
    float x3 = x * x * x;
    return 0.5f * x * (1.0f + tanhf(0.7978845608028654f * (x + 0.044715f * x3)));
}

// ---------------------------------------------------------------------------
// Weight transpose + fp32->fp16 convert: W[K][N] -> Wt[N][K]
// ---------------------------------------------------------------------------
__global__ void k_transpose(const float* __restrict__ W, __half* __restrict__ Wt,
                            int K, int N) {
    int i = blockIdx.x * 256 + threadIdx.x;
    if (i >= K * N) return;
    int n = i / K;
    int k = i - n * K;
    Wt[i] = __float2half(W[(size_t)k * N + n]);
}

// ---------------------------------------------------------------------------
// Kernel 1: LN1 + roll(-4,-4) + window partition
// ---------------------------------------------------------------------------
__global__ __launch_bounds__(128) void k_ln1(const float* __restrict__ hs,
                                             const float* __restrict__ g,
                                             const float* __restrict__ b,
                                             __half* __restrict__ xw) {
    int n    = blockIdx.x;
    int bimg = n >> 12;
    int rem  = n & 4095;
    int wid  = rem >> 6, t = rem & 63;
    int wy = wid >> 3, wx = wid & 7;
    int hr = wy * 8 + (t >> 3), wr = wx * 8 + (t & 7);
    int h0 = (hr + SHIFT) & 63, w0 = (wr + SHIFT) & 63;
    size_t src = ((size_t)(bimg << 12) + (h0 << 6) + w0) * CDIM;

    int tid = threadIdx.x;
    float4 v = ((const float4*)(hs + src))[tid];
    float s  = v.x + v.y + v.z + v.w;
    float s2 = v.x * v.x + v.y * v.y + v.z * v.z + v.w * v.w;
#pragma unroll
    for (int o = 16; o; o >>= 1) {
        s  += __shfl_xor_sync(0xffffffffu, s,  o);
        s2 += __shfl_xor_sync(0xffffffffu, s2, o);
    }
    __shared__ float rs[4], rq[4];
    int warp = tid >> 5, lane = tid & 31;
    if (lane == 0) { rs[warp] = s; rq[warp] = s2; }
    __syncthreads();
    s  = rs[0] + rs[1] + rs[2] + rs[3];
    s2 = rq[0] + rq[1] + rq[2] + rq[3];
    float mean = s * (1.0f / 512.0f);
    float var  = s2 * (1.0f / 512.0f) - mean * mean;
    float rstd = rsqrtf(var + 1e-5f);

    int c = tid * 4;
    float4 gv = ((const float4*)g)[tid];
    float4 bv = ((const float4*)b)[tid];
    __half2* o = (__half2*)(xw + (size_t)n * CDIM + c);
    o[0] = __floats2half2_rn((v.x - mean) * rstd * gv.x + bv.x,
                             (v.y - mean) * rstd * gv.y + bv.y);
    o[1] = __floats2half2_rn((v.z - mean) * rstd * gv.z + bv.z,
                             (v.w - mean) * rstd * gv.w + bv.w);
}

// ---------------------------------------------------------------------------
// HMMA GEMM (unchanged from R4): 128x128 tile, BK=32, 4-stage ring, 2 CTAs/SM
// ---------------------------------------------------------------------------
#define KW    40
#define ROWB  80
#define STGB  (128 * ROWB)
#define NSTG  4
#define GSM_BIAS 0
#define GSM_A    1024
#define GSM_B    (GSM_A + NSTG * STGB)
#define GSM_TOTAL (GSM_B + NSTG * STGB)

__device__ __forceinline__ void g4_load(char* smem, const __half* A, const __half* Bt,
                                        size_t aBase, size_t bBase, int K,
                                        int st, int ko, int tid) {
    char* pa = smem + GSM_A + st * STGB;
    char* pb = smem + GSM_B + st * STGB;
#pragma unroll
    for (int j = 0; j < 2; j++) {
        int c = tid + 256 * j;
        int r = c >> 2, sg = c & 3;
        cp16(pa + r * ROWB + sg * 16, A + aBase + (size_t)r * K + ko + sg * 8);
        cp16(pb + r * ROWB + sg * 16, Bt + bBase + (size_t)r * K + ko + sg * 8);
    }
}

template <int EPI>
__global__ __launch_bounds__(256, 2) void gemm16(const __half* __restrict__ A,
                                                 const __half* __restrict__ Bt,
                                                 const float* __restrict__ bias,
                                                 const float* __restrict__ res,
                                                 void* __restrict__ outp,
                                                 int M, int N, int K) {
    extern __shared__ char smem[];
    int tid = threadIdx.x;
    int bx = blockIdx.x, by = blockIdx.y;
    size_t aBase = (size_t)by * 128 * K;
    size_t bBase = (size_t)bx * 128 * K;

    if (tid < 128) ((float*)(smem + GSM_BIAS))[tid] = bias[bx * 128 + tid];

    int niter = K >> 5;

#pragma unroll
    for (int st = 0; st < 3; st++) {
        g4_load(smem, A, Bt, aBase, bBase, K, st, st << 5, tid);
        cp_commit();
    }

    int warp = tid >> 5, lane = tid & 31;
    int wm = warp >> 1, wn = warp & 1;

    float acc[2][8][4];
#pragma unroll
    for (int mi = 0; mi < 2; mi++)
#pragma unroll
        for (int ni = 0; ni < 8; ni++)
#pragma unroll
            for (int j = 0; j < 4; j++) acc[mi][ni][j] = 0.0f;

    int aRow = wm * 32 + (lane & 7) + ((lane >> 3) & 1) * 8;
    int aCol = (lane >> 4) * 8;
    int bRow = wn * 64 + (lane & 7) + (lane >> 4) * 8;
    int bCol = ((lane >> 3) & 1) * 8;

    for (int it = 0; it < niter; ++it) {
        cp_wait2();
        __syncthreads();
        if (it + 3 < niter)
            g4_load(smem, A, Bt, aBase, bBase, K, (it + 3) & 3, (it + 3) << 5, tid);
        cp_commit();

        int st = it & 3;
        const __half* sa = (const __half*)(smem + GSM_A + st * STGB);
        const __half* sb = (const __half*)(smem + GSM_B + st * STGB);
#pragma unroll
        for (int ks = 0; ks < 2; ++ks) {
            uint32_t a[2][4];
#pragma unroll
            for (int mi = 0; mi < 2; mi++)
                ldm4(a[mi][0], a[mi][1], a[mi][2], a[mi][3],
                     sa + (size_t)(aRow + mi * 16) * KW + ks * 16 + aCol);
            uint32_t bf[8][2];
#pragma unroll
            for (int nj = 0; nj < 4; nj++) {
                uint32_t q0, q1, q2, q3;
                ldm4(q0, q1, q2, q3,
                     sb + (size_t)(bRow + nj * 16) * KW + ks * 16 + bCol);
                bf[nj * 2][0] = q0; bf[nj * 2][1] = q1;
                bf[nj * 2 + 1][0] = q2; bf[nj * 2 + 1][1] = q3;
            }
#pragma unroll
            for (int mi = 0; mi < 2; mi++)
#pragma unroll
                for (int ni = 0; ni < 8; ni++)
                    mma16816(acc[mi][ni][0], acc[mi][ni][1], acc[mi][ni][2], acc[mi][ni][3],
                             a[mi][0], a[mi][1], a[mi][2], a[mi][3],
                             bf[ni][0], bf[ni][1]);
        }
    }

    const float* sbias = (const float*)(smem + GSM_BIAS);
    int gm0 = by * 128 + wm * 32;
    int gn0 = bx * 128 + wn * 64;
    int ln0 = wn * 64;
#pragma unroll
    for (int mi = 0; mi < 2; mi++) {
#pragma unroll
        for (int ni = 0; ni < 8; ni++) {
            int row = gm0 + mi * 16 + (lane >> 2);
            int col = gn0 + ni * 8 + (lane & 3) * 2;
            int lcol = ln0 + ni * 8 + (lane & 3) * 2;
            float bv0 = sbias[lcol], bv1 = sbias[lcol + 1];
#pragma unroll
            for (int hf = 0; hf < 2; hf++) {
                int gr = row + hf * 8;
                float v0 = acc[mi][ni][hf * 2 + 0] + bv0;
                float v1 = acc[mi][ni][hf * 2 + 1] + bv1;
                size_t off = (size_t)gr * N + col;
                if constexpr (EPI == 0) {
                    *(__half2*)((__half*)outp + off) = __floats2half2_rn(v0, v1);
                } else if constexpr (EPI == 1) {
                    *(float2*)((float*)outp + off) = make_float2(v0, v1);
                } else if constexpr (EPI == 2) {
                    *(__half2*)((__half*)outp + off) =
                        __floats2half2_rn(gelu_tanh(v0), gelu_tanh(v1));
                } else {
                    v0 += res[off];
                    v1 += res[off + 1];
                    *(float2*)((float*)outp + off) = make_float2(v0, v1);
                }
            }
        }
    }
}

// ---------------------------------------------------------------------------
// Kernel 3: HMMA attention. One WARP per (window, head); block = 4 heads.
// Q,K,V staged to smem (80B row stride); scores/P/O register-resident.
// ---------------------------------------------------------------------------
#define ATT_SCALE 0.17677669529663687f
#define AH_HALVES 7680            // 3 tiles x 64 rows x 40 halves
#define ASM_SID   61440           // byte offset of sid[64]
#define ASM_TOTAL 61696

__global__ __launch_bounds__(128, 2) void k_attn_mma(const __half* __restrict__ qkv,
                                                     __half* __restrict__ attn) {
    extern __shared__ char asmem[];
    int w = blockIdx.x, hg = blockIdx.y;
    int tid = threadIdx.x, wi = tid >> 5, lane = tid & 31;
    int head = hg * 4 + wi;

    __half* sh = (__half*)asmem + wi * AH_HALVES;      // Q @0, K @2560, V @5120
    int* sid = (int*)(asmem + ASM_SID);

    // stage Q/K/V for this head: 64 rows x 32 halves each, row stride 40 halves
    const __half* base = qkv + (size_t)w * 64 * 1536 + head * 32;
#pragma unroll
    for (int i = 0; i < 8; i++) {
        int c = lane + 32 * i;
        int r = c >> 2, sg = c & 3;
        const __half* src = base + (size_t)r * 1536 + sg * 8;
        cp16(&sh[r * 40 + sg * 8], src);
        cp16(&sh[2560 + r * 40 + sg * 8], src + 512);
        cp16(&sh[5120 + r * 40 + sg * 8], src + 1024);
    }
    cp_commit();
    if (tid < 64) {
        int wim = w & 63;
        int wy = wim >> 3, wx = wim & 7;
        int hh = wy * 8 + (tid >> 3), ww = wx * 8 + (tid & 7);
        int rh = (hh < 56) ? 0 : ((hh < 60) ? 1 : 2);
        int rw = (ww < 56) ? 0 : ((ww < 60) ? 1 : 2);
        sid[tid] = rh * 3 + rw;
    }
    cp_wait0();
    __syncthreads();

    // ---- scores = Q @ K^T (64x64x32) ----
    int aRow = (lane & 7) + ((lane >> 3) & 1) * 8;
    int aCol = (lane >> 4) * 8;
    int bRow = (lane & 7) + (lane >> 4) * 8;
    int bCol = ((lane >> 3) & 1) * 8;

    uint32_t qa[4][2][4];
#pragma unroll
    for (int mi = 0; mi < 4; mi++)
#pragma unroll
        for (int ks = 0; ks < 2; ks++)
            ldm4(qa[mi][ks][0], qa[mi][ks][1], qa[mi][ks][2], qa[mi][ks][3],
                 &sh[(mi * 16 + aRow) * 40 + ks * 16 + aCol]);

    float sc[4][8][4];
#pragma unroll
    for (int mi = 0; mi < 4; mi++)
#pragma unroll
        for (int ni = 0; ni < 8; ni++)
#pragma unroll
            for (int j = 0; j < 4; j++) sc[mi][ni][j] = 0.0f;

    const __half* Ksh = sh + 2560;
#pragma unroll
    for (int nh = 0; nh < 2; nh++) {
        uint32_t kb[4][2][2];
#pragma unroll
        for (int nj2 = 0; nj2 < 2; nj2++)
#pragma unroll
            for (int ks = 0; ks < 2; ks++) {
                uint32_t q0, q1, q2, q3;
                ldm4(q0, q1, q2, q3,
                     &Ksh[(nh * 32 + nj2 * 16 + bRow) * 40 + ks * 16 + bCol]);
                kb[nj2 * 2][ks][0] = q0;     kb[nj2 * 2][ks][1] = q1;
                kb[nj2 * 2 + 1][ks][0] = q2; kb[nj2 * 2 + 1][ks][1] = q3;
            }
#pragma unroll
        for (int mi = 0; mi < 4; mi++)
#pragma unroll
            for (int f = 0; f < 4; f++)
#pragma unroll
                for (int ks = 0; ks < 2; ks++)
                    mma16816(sc[mi][nh * 4 + f][0], sc[mi][nh * 4 + f][1],
                             sc[mi][nh * 4 + f][2], sc[mi][nh * 4 + f][3],
                             qa[mi][ks][0], qa[mi][ks][1], qa[mi][ks][2], qa[mi][ks][3],
                             kb[f][ks][0], kb[f][ks][1]);
    }

    // ---- mask + softmax (rows spread over lane quads) ----
    int rsub = lane >> 2;
    int cbase = (lane & 3) * 2;
    int cid[16];
#pragma unroll
    for (int ni = 0; ni < 8; ni++) {
        cid[2 * ni]     = sid[ni * 8 + cbase];
        cid[2 * ni + 1] = sid[ni * 8 + cbase + 1];
    }

    float inv1[4], inv2[4];
    uint32_t pa[4][4][4];
#pragma unroll
    for (int mi = 0; mi < 4; mi++) {
        int rid1 = sid[mi * 16 + rsub];
        int rid2 = sid[mi * 16 + rsub + 8];
#pragma unroll
        for (int ni = 0; ni < 8; ni++) {
            sc[mi][ni][0] = (cid[2 * ni]     == rid1) ? sc[mi][ni][0] * ATT_SCALE : -10000.0f;
            sc[mi][ni][1] = (cid[2 * ni + 1] == rid1) ? sc[mi][ni][1] * ATT_SCALE : -10000.0f;
            sc[mi][ni][2] = (cid[2 * ni]     == rid2) ? sc[mi][ni][2] * ATT_SCALE : -10000.0f;
            sc[mi][ni][3] = (cid[2 * ni + 1] == rid2) ? sc[mi][ni][3] * ATT_SCALE : -10000.0f;
        }
        float m1 = -1e30f, m2 = -1e30f;
#pragma unroll
        for (int ni = 0; ni < 8; ni++) {
            m1 = fmaxf(m1, fmaxf(sc[mi][ni][0], sc[mi][ni][1]));
            m2 = fmaxf(m2, fmaxf(sc[mi][ni][2], sc[mi][ni][3]));
        }
        m1 = fmaxf(m1, __shfl_xor_sync(0xffffffffu, m1, 1));
        m1 = fmaxf(m1, __shfl_xor_sync(0xffffffffu, m1, 2));
        m2 = fmaxf(m2, __shfl_xor_sync(0xffffffffu, m2, 1));
        m2 = fmaxf(m2, __shfl_xor_sync(0xffffffffu, m2, 2));
        float s1 = 0.0f, s2 = 0.0f;
#pragma unroll
        for (int ni = 0; ni < 8; ni++) {
            float e0 = __expf(sc[mi][ni][0] - m1);
            float e1 = __expf(sc[mi][ni][1] - m1);
            float e2 = __expf(sc[mi][ni][2] - m2);
            float e3 = __expf(sc[mi][ni][3] - m2);
            sc[mi][ni][0] = e0; sc[mi][ni][1] = e1;
            sc[mi][ni][2] = e2; sc[mi][ni][3] = e3;
            s1 += e0 + e1; s2 += e2 + e3;
        }
        s1 += __shfl_xor_sync(0xffffffffu, s1, 1);
        s1 += __shfl_xor_sync(0xffffffffu, s1, 2);
        s2 += __shfl_xor_sync(0xffffffffu, s2, 1);
        s2 += __shfl_xor_sync(0xffffffffu, s2, 2);
        inv1[mi] = 1.0f / s1;
        inv2[mi] = 1.0f / s2;
        // pack unnormalized P into A fragments (C-frag -> A-frag identity)
#pragma unroll
        for (int kj = 0; kj < 4; kj++) {
            __half2 h0 = __floats2half2_rn(sc[mi][2 * kj][0], sc[mi][2 * kj][1]);
            __half2 h1 = __floats2half2_rn(sc[mi][2 * kj][2], sc[mi][2 * kj][3]);
            __half2 h2 = __floats2half2_rn(sc[mi][2 * kj + 1][0], sc[mi][2 * kj + 1][1]);
            __half2 h3 = __floats2half2_rn(sc[mi][2 * kj + 1][2], sc[mi][2 * kj + 1][3]);
            pa[mi][kj][0] = *(uint32_t*)&h0;
            pa[mi][kj][1] = *(uint32_t*)&h1;
            pa[mi][kj][2] = *(uint32_t*)&h2;
            pa[mi][kj][3] = *(uint32_t*)&h3;
        }
    }

    // ---- O = P @ V (64x32x64), V via ldmatrix.trans ----
    float ot[4][4][4];
#pragma unroll
    for (int mi = 0; mi < 4; mi++)
#pragma unroll
        for (int nj = 0; nj < 4; nj++)
#pragma unroll
            for (int j = 0; j < 4; j++) ot[mi][nj][j] = 0.0f;

    const __half* Vsh = sh + 5120;
#pragma unroll
    for (int kj = 0; kj < 4; kj++) {
        uint32_t vb[4][2];
#pragma unroll
        for (int g = 0; g < 2; g++) {
            uint32_t q0, q1, q2, q3;
            ldm4t(q0, q1, q2, q3,
                  &Vsh[(kj * 16 + (lane & 7) + ((lane >> 3) & 1) * 8) * 40 +
                       g * 16 + (lane >> 4) * 8]);
            vb[2 * g][0] = q0;     vb[2 * g][1] = q1;
            vb[2 * g + 1][0] = q2; vb[2 * g + 1][1] = q3;
        }
#pragma unroll
        for (int mi = 0; mi < 4; mi++)
#pragma unroll
            for (int nj = 0; nj < 4; nj++)
                mma16816(ot[mi][nj][0], ot[mi][nj][1], ot[mi][nj][2], ot[mi][nj][3],
                         pa[mi][kj][0], pa[mi][kj][1], pa[mi][kj][2], pa[mi][kj][3],
                         vb[nj][0], vb[nj][1]);
    }

    // ---- epilogue: normalize + store fp16 ----
#pragma unroll
    for (int mi = 0; mi < 4; mi++) {
        __half* o1 = attn + (size_t)(w * 64 + mi * 16 + rsub) * 512 + head * 32 + cbase;
        __half* o2 = o1 + (size_t)8 * 512;
#pragma unroll
        for (int nj = 0; nj < 4; nj++) {
            *(__half2*)(o1 + nj * 8) =
                __floats2half2_rn(ot[mi][nj][0] * inv1[mi], ot[mi][nj][1] * inv1[mi]);
            *(__half2*)(o2 + nj * 8) =
                __floats2half2_rn(ot[mi][nj][2] * inv2[mi], ot[mi][nj][3] * inv2[mi]);
        }
    }
}

// ---------------------------------------------------------------------------
// Kernel 5: window reverse + roll(+4,+4) + residual + LN2
// ---------------------------------------------------------------------------
__global__ __launch_bounds__(128) void k_rev_ln2(const float* __restrict__ hs,
                                                 const float* __restrict__ proj,
                                                 const float* __restrict__ g,
                                                 const float* __restrict__ b,
                                                 float* __restrict__ x,
                                                 __half* __restrict__ hout) {
    int m = blockIdx.x;
    int bimg = m >> 12;
    int hw = m & 4095;
    int h0 = hw >> 6, w0 = hw & 63;
    int hr = (h0 + 64 - SHIFT) & 63, wr = (w0 + 64 - SHIFT) & 63;
    int wy = hr >> 3, rr = hr & 7, wx = wr >> 3, cc = wr & 7;
    int n = (bimg << 12) + ((wy * 8 + wx) << 6) + (rr * 8 + cc);

    int tid = threadIdx.x;
    float4 a = ((const float4*)(hs + (size_t)m * CDIM))[tid];
    float4 p = ((const float4*)(proj + (size_t)n * CDIM))[tid];
    float4 v = make_float4(a.x + p.x, a.y + p.y, a.z + p.z, a.w + p.w);
    ((float4*)(x + (size_t)m * CDIM))[tid] = v;

    float s  = v.x + v.y + v.z + v.w;
    float s2 = v.x * v.x + v.y * v.y + v.z * v.z + v.w * v.w;
#pragma unroll
    for (int o = 16; o; o >>= 1) {
        s  += __shfl_xor_sync(0xffffffffu, s,  o);
        s2 += __shfl_xor_sync(0xffffffffu, s2, o);
    }
    __shared__ float rs[4], rq[4];
    int warp = tid >> 5, lane = tid & 31;
    if (lane == 0) { rs[warp] = s; rq[warp] = s2; }
    __syncthreads();
    s  = rs[0] + rs[1] + rs[2] + rs[3];
    s2 = rq[0] + rq[1] + rq[2] + rq[3];
    float mean = s * (1.0f / 512.0f);
    float var  = s2 * (1.0f / 512.0f) - mean * mean;
    float rstd = rsqrtf(var + 1e-5f);

    int c = tid * 4;
    float4 gv = ((const float4*)g)[tid];
    float4 bv = ((const float4*)b)[tid];
    __half2* o = (__half2*)(hout + (size_t)m * CDIM + c);
    o[0] = __floats2half2_rn((v.x - mean) * rstd * gv.x + bv.x,
                             (v.y - mean) * rstd * gv.y + bv.y);
    o[1] = __floats2half2_rn((v.z - mean) * rstd * gv.z + bv.z,
                             (v.w - mean) * rstd * gv.w + bv.w);
}

// ---------------------------------------------------------------------------
// Host launcher
// ---------------------------------------------------------------------------
extern "C" void kernel_launch(void* const* d_in, const int* in_sizes, int n_in,
                              void* d_out, int out_size) {
    const float* hs   = (const float*)d_in[0];
    const float* Wqkv = (const float*)d_in[1];
    const float* bqkv = (const float*)d_in[2];
    const float* Wo   = (const float*)d_in[3];
    const float* bo   = (const float*)d_in[4];
    const float* ln1g = (const float*)d_in[5];
    const float* ln1b = (const float*)d_in[6];
    const float* ln2g = (const float*)d_in[7];
    const float* ln2b = (const float*)d_in[8];
    const float* W1   = (const float*)d_in[9];
    const float* b1   = (const float*)d_in[10];
    const float* W2   = (const float*)d_in[11];
    const float* b2   = (const float*)d_in[12];

    __half *xw, *qkv, *attn, *hbuf, *ff, *wqkvT, *woT, *w1T, *w2T;
    float *proj, *xbuf;
    cudaGetSymbolAddress((void**)&xw,    g_xw);
    cudaGetSymbolAddress((void**)&qkv,   g_qkv);
    cudaGetSymbolAddress((void**)&attn,  g_attn);
    cudaGetSymbolAddress((void**)&proj,  g_proj);
    cudaGetSymbolAddress((void**)&xbuf,  g_x);
    cudaGetSymbolAddress((void**)&hbuf,  g_h);
    cudaGetSymbolAddress((void**)&ff,    g_ff);
    cudaGetSymbolAddress((void**)&wqkvT, g_wqkvT);
    cudaGetSymbolAddress((void**)&woT,   g_woT);
    cudaGetSymbolAddress((void**)&w1T,   g_w1T);
    cudaGetSymbolAddress((void**)&w2T,   g_w2T);

    cudaFuncSetAttribute(gemm16<0>, cudaFuncAttributeMaxDynamicSharedMemorySize, GSM_TOTAL);
    cudaFuncSetAttribute(gemm16<1>, cudaFuncAttributeMaxDynamicSharedMemorySize, GSM_TOTAL);
    cudaFuncSetAttribute(gemm16<2>, cudaFuncAttributeMaxDynamicSharedMemorySize, GSM_TOTAL);
    cudaFuncSetAttribute(gemm16<3>, cudaFuncAttributeMaxDynamicSharedMemorySize, GSM_TOTAL);
    cudaFuncSetAttribute(k_attn_mma, cudaFuncAttributeMaxDynamicSharedMemorySize, ASM_TOTAL);

    // weight transposes (fp32 -> fp16, [K,N] -> [N,K])
    k_transpose<<<(512 * 1536 + 255) / 256, 256>>>(Wqkv, wqkvT, 512, 1536);
    k_transpose<<<(512 * 512  + 255) / 256, 256>>>(Wo,   woT,   512, 512);
    k_transpose<<<(512 * 2048 + 255) / 256, 256>>>(W1,   w1T,   512, 2048);
    k_transpose<<<(2048 * 512 + 255) / 256, 256>>>(W2,   w2T,   2048, 512);

    // 1. LN1 + shift + partition
    k_ln1<<<MTOK, 128>>>(hs, ln1g, ln1b, xw);

    // 2. QKV GEMM: [131072,512] x [512,1536] -> fp16
    gemm16<0><<<dim3(1536 / 128, MTOK / 128), 256, GSM_TOTAL>>>(
        xw, wqkvT, bqkv, nullptr, qkv, MTOK, 1536, 512);

    // 3. attention (HMMA, 1 warp per window-head)
    k_attn_mma<<<dim3(2048, 4), 128, ASM_TOTAL>>>(qkv, attn);

    // 4. out projection: [131072,512] x [512,512] -> fp32
    gemm16<1><<<dim3(512 / 128, MTOK / 128), 256, GSM_TOTAL>>>(
        attn, woT, bo, nullptr, proj, MTOK, 512, 512);

    // 5. reverse + residual + LN2
    k_rev_ln2<<<MTOK, 128>>>(hs, proj, ln2g, ln2b, xbuf, hbuf);

    // 6. MLP up + gelu: [131072,512] x [512,2048] -> fp16
    gemm16<2><<<dim3(2048 / 128, MTOK / 128), 256, GSM_TOTAL>>>(
        hbuf, w1T, b1, nullptr, ff, MTOK, 2048, 512);

    // 7. MLP down + residual: [131072,2048] x [2048,512] -> fp32 d_out
    gemm16<3><<<dim3(512 / 128, MTOK / 128), 256, GSM_TOTAL>>>(
        ff, w2T, b2, xbuf, d_out, MTOK, 512, 2048);
}

// round 6
// speedup vs baseline: 1.5745x; 1.0582x over previous
#include <cuda_runtime.h>
#include <cuda_fp16.h>
#include <cstdint>

// ---------------------------------------------------------------------------
// Problem constants
// ---------------------------------------------------------------------------
#define BATCH 32
#define CDIM  512
#define NHEAD 16
#define SHIFT 4
#define SEQ   64
#define HEADD 32
#define FFDIM 2048
#define MTOK  131072

// ---------------------------------------------------------------------------
// Scratch
// ---------------------------------------------------------------------------
__device__ __half g_xw  [ (size_t)MTOK * CDIM  ];
__device__ __half g_qkv [ (size_t)MTOK * 3*CDIM];
__device__ __half g_attn[ (size_t)MTOK * CDIM  ];
__device__ float  g_proj[ (size_t)MTOK * CDIM  ];
__device__ float  g_x   [ (size_t)MTOK * CDIM  ];
__device__ __half g_h   [ (size_t)MTOK * CDIM  ];
__device__ __half g_ff  [ (size_t)MTOK * FFDIM ];
__device__ __half g_wqkvT[3*CDIM * CDIM];
__device__ __half g_woT  [CDIM * CDIM];
__device__ __half g_w1T  [FFDIM * CDIM];
__device__ __half g_w2T  [CDIM * FFDIM];

// ---------------------------------------------------------------------------
// Helpers
// ---------------------------------------------------------------------------
__device__ __forceinline__ void cp16(void* smem, const void* gmem) {
    unsigned s = (unsigned)__cvta_generic_to_shared(smem);
    asm volatile("cp.async.cg.shared.global [%0], [%1], 16;\n" :: "r"(s), "l"(gmem));
}
__device__ __forceinline__ void cp_commit() { asm volatile("cp.async.commit_group;\n"); }
__device__ __forceinline__ void cp_wait2()  { asm volatile("cp.async.wait_group 2;\n"); }
__device__ __forceinline__ void cp_wait0()  { asm volatile("cp.async.wait_group 0;\n"); }

__device__ __forceinline__ void ldm4(uint32_t& r0, uint32_t& r1, uint32_t& r2, uint32_t& r3,
                                     const __half* p) {
    unsigned s = (unsigned)__cvta_generic_to_shared(p);
    asm volatile("ldmatrix.sync.aligned.m8n8.x4.shared.b16 {%0,%1,%2,%3},[%4];\n"
                 : "=r"(r0), "=r"(r1), "=r"(r2), "=r"(r3) : "r"(s));
}
__device__ __forceinline__ void ldm4t(uint32_t& r0, uint32_t& r1, uint32_t& r2, uint32_t& r3,
                                      const __half* p) {
    unsigned s = (unsigned)__cvta_generic_to_shared(p);
    asm volatile("ldmatrix.sync.aligned.m8n8.x4.trans.shared.b16 {%0,%1,%2,%3},[%4];\n"
                 : "=r"(r0), "=r"(r1), "=r"(r2), "=r"(r3) : "r"(s));
}
__device__ __forceinline__ void mma16816(float& c0, float& c1, float& c2, float& c3,
                                         uint32_t a0, uint32_t a1, uint32_t a2, uint32_t a3,
                                         uint32_t b0, uint32_t b1) {
    asm volatile("mma.sync.aligned.m16n8k16.row.col.f32.f16.f16.f32 "
                 "{%0,%1,%2,%3},{%4,%5,%6,%7},{%8,%9},{%0,%1,%2,%3};\n"
                 : "+f"(c0), "+f"(c1), "+f"(c2), "+f"(c3)
                 : "r"(a0), "r"(a1), "r"(a2), "r"(a3), "r"(b0), "r"(b1));
}
__device__ __forceinline__ float gelu_tanh(float x) {
    float x3 = x * x * x;
    return 0.5f * x * (1.0f + tanhf(0.7978845608028654f * (x + 0.044715f * x3)));
}

// ---------------------------------------------------------------------------
// Weight transpose + fp32->fp16 convert: W[K][N] -> Wt[N][K]
// ---------------------------------------------------------------------------
__global__ void k_transpose(const float* __restrict__ W, __half* __restrict__ Wt,
                            int K, int N) {
    int i = blockIdx.x * 256 + threadIdx.x;
    if (i >= K * N) return;
    int n = i / K;
    int k = i - n * K;
    Wt[i] = __float2half(W[(size_t)k * N + n]);
}

// ---------------------------------------------------------------------------
// Kernel 1: LN1 + roll(-4,-4) + window partition
// ---------------------------------------------------------------------------
__global__ __launch_bounds__(128) void k_ln1(const float* __restrict__ hs,
                                             const float* __restrict__ g,
                                             const float* __restrict__ b,
                                             __half* __restrict__ xw) {
    int n    = blockIdx.x;
    int bimg = n >> 12;
    int rem  = n & 4095;
    int wid  = rem >> 6, t = rem & 63;
    int wy = wid >> 3, wx = wid & 7;
    int hr = wy * 8 + (t >> 3), wr = wx * 8 + (t & 7);
    int h0 = (hr + SHIFT) & 63, w0 = (wr + SHIFT) & 63;
    size_t src = ((size_t)(bimg << 12) + (h0 << 6) + w0) * CDIM;

    int tid = threadIdx.x;
    float4 v = ((const float4*)(hs + src))[tid];
    float s  = v.x + v.y + v.z + v.w;
    float s2 = v.x * v.x + v.y * v.y + v.z * v.z + v.w * v.w;
#pragma unroll
    for (int o = 16; o; o >>= 1) {
        s  += __shfl_xor_sync(0xffffffffu, s,  o);
        s2 += __shfl_xor_sync(0xffffffffu, s2, o);
    }
    __shared__ float rs[4], rq[4];
    int warp = tid >> 5, lane = tid & 31;
    if (lane == 0) { rs[warp] = s; rq[warp] = s2; }
    __syncthreads();
    s  = rs[0] + rs[1] + rs[2] + rs[3];
    s2 = rq[0] + rq[1] + rq[2] + rq[3];
    float mean = s * (1.0f / 512.0f);
    float var  = s2 * (1.0f / 512.0f) - mean * mean;
    float rstd = rsqrtf(var + 1e-5f);

    int c = tid * 4;
    float4 gv = ((const float4*)g)[tid];
    float4 bv = ((const float4*)b)[tid];
    __half2* o = (__half2*)(xw + (size_t)n * CDIM + c);
    o[0] = __floats2half2_rn((v.x - mean) * rstd * gv.x + bv.x,
                             (v.y - mean) * rstd * gv.y + bv.y);
    o[1] = __floats2half2_rn((v.z - mean) * rstd * gv.z + bv.z,
                             (v.w - mean) * rstd * gv.w + bv.w);
}

// ---------------------------------------------------------------------------
// HMMA GEMM: 128x128 CTA tile, 128 threads (4 warps, 64x64 warp tiles),
// BK=32, 4-stage cp.async ring, 2 CTAs/SM.
// EPI: 0 +bias->fp16 | 1 +bias->fp32 | 2 gelu->fp16 | 3 +res->fp32
// ---------------------------------------------------------------------------
#define KW    40
#define ROWB  80
#define STGB  (128 * ROWB)
#define NSTG  4
#define GSM_BIAS 0
#define GSM_A    1024
#define GSM_B    (GSM_A + NSTG * STGB)
#define GSM_TOTAL (GSM_B + NSTG * STGB)

__device__ __forceinline__ void g4_load(char* smem, const __half* A, const __half* Bt,
                                        size_t aBase, size_t bBase, int K,
                                        int st, int ko, int tid) {
    char* pa = smem + GSM_A + st * STGB;
    char* pb = smem + GSM_B + st * STGB;
#pragma unroll
    for (int j = 0; j < 4; j++) {
        int c = tid + 128 * j;
        int r = c >> 2, sg = c & 3;
        cp16(pa + r * ROWB + sg * 16, A + aBase + (size_t)r * K + ko + sg * 8);
        cp16(pb + r * ROWB + sg * 16, Bt + bBase + (size_t)r * K + ko + sg * 8);
    }
}

template <int EPI>
__global__ __launch_bounds__(128, 2) void gemm16(const __half* __restrict__ A,
                                                 const __half* __restrict__ Bt,
                                                 const float* __restrict__ bias,
                                                 const float* __restrict__ res,
                                                 void* __restrict__ outp,
                                                 int M, int N, int K) {
    extern __shared__ char smem[];
    int tid = threadIdx.x;
    int bx = blockIdx.x, by = blockIdx.y;
    size_t aBase = (size_t)by * 128 * K;
    size_t bBase = (size_t)bx * 128 * K;

    ((float*)(smem + GSM_BIAS))[tid] = bias[bx * 128 + tid];

    int niter = K >> 5;

#pragma unroll
    for (int st = 0; st < 3; st++) {
        g4_load(smem, A, Bt, aBase, bBase, K, st, st << 5, tid);
        cp_commit();
    }

    int warp = tid >> 5, lane = tid & 31;
    int wm = warp >> 1, wn = warp & 1;          // 2x2 warps; warp tile 64x64

    float acc[4][8][4];
#pragma unroll
    for (int mi = 0; mi < 4; mi++)
#pragma unroll
        for (int ni = 0; ni < 8; ni++)
#pragma unroll
            for (int j = 0; j < 4; j++) acc[mi][ni][j] = 0.0f;

    int aRow = wm * 64 + (lane & 7) + ((lane >> 3) & 1) * 8;
    int aCol = (lane >> 4) * 8;
    int bRow = wn * 64 + (lane & 7) + (lane >> 4) * 8;
    int bCol = ((lane >> 3) & 1) * 8;

    for (int it = 0; it < niter; ++it) {
        cp_wait2();
        __syncthreads();
        if (it + 3 < niter)
            g4_load(smem, A, Bt, aBase, bBase, K, (it + 3) & 3, (it + 3) << 5, tid);
        cp_commit();

        int st = it & 3;
        const __half* sa = (const __half*)(smem + GSM_A + st * STGB);
        const __half* sb = (const __half*)(smem + GSM_B + st * STGB);
#pragma unroll
        for (int ks = 0; ks < 2; ++ks) {
            uint32_t a[4][4];
#pragma unroll
            for (int mi = 0; mi < 4; mi++)
                ldm4(a[mi][0], a[mi][1], a[mi][2], a[mi][3],
                     sa + (size_t)(aRow + mi * 16) * KW + ks * 16 + aCol);
            uint32_t bf[8][2];
#pragma unroll
            for (int nj = 0; nj < 4; nj++) {
                uint32_t q0, q1, q2, q3;
                ldm4(q0, q1, q2, q3,
                     sb + (size_t)(bRow + nj * 16) * KW + ks * 16 + bCol);
                bf[nj * 2][0] = q0; bf[nj * 2][1] = q1;
                bf[nj * 2 + 1][0] = q2; bf[nj * 2 + 1][1] = q3;
            }
#pragma unroll
            for (int mi = 0; mi < 4; mi++)
#pragma unroll
                for (int ni = 0; ni < 8; ni++)
                    mma16816(acc[mi][ni][0], acc[mi][ni][1], acc[mi][ni][2], acc[mi][ni][3],
                             a[mi][0], a[mi][1], a[mi][2], a[mi][3],
                             bf[ni][0], bf[ni][1]);
        }
    }

    // epilogue
    const float* sbias = (const float*)(smem + GSM_BIAS);
    int gm0 = by * 128 + wm * 64;
    int gn0 = bx * 128 + wn * 64;
    int ln0 = wn * 64;
#pragma unroll
    for (int mi = 0; mi < 4; mi++) {
#pragma unroll
        for (int ni = 0; ni < 8; ni++) {
            int row = gm0 + mi * 16 + (lane >> 2);
            int col = gn0 + ni * 8 + (lane & 3) * 2;
            int lcol = ln0 + ni * 8 + (lane & 3) * 2;
            float bv0 = sbias[lcol], bv1 = sbias[lcol + 1];
#pragma unroll
            for (int hf = 0; hf < 2; hf++) {
                int gr = row + hf * 8;
                float v0 = acc[mi][ni][hf * 2 + 0] + bv0;
                float v1 = acc[mi][ni][hf * 2 + 1] + bv1;
                size_t off = (size_t)gr * N + col;
                if constexpr (EPI == 0) {
                    *(__half2*)((__half*)outp + off) = __floats2half2_rn(v0, v1);
                } else if constexpr (EPI == 1) {
                    *(float2*)((float*)outp + off) = make_float2(v0, v1);
                } else if constexpr (EPI == 2) {
                    *(__half2*)((__half*)outp + off) =
                        __floats2half2_rn(gelu_tanh(v0), gelu_tanh(v1));
                } else {
                    v0 += res[off];
                    v1 += res[off + 1];
                    *(float2*)((float*)outp + off) = make_float2(v0, v1);
                }
            }
        }
    }
}

// ---------------------------------------------------------------------------
// Kernel 3: HMMA attention. One WARP per (window, head); block = 4 heads.
// ---------------------------------------------------------------------------
#define ATT_SCALE 0.17677669529663687f
#define AH_HALVES 7680
#define ASM_SID   61440
#define ASM_TOTAL 61696

__global__ __launch_bounds__(128, 2) void k_attn_mma(const __half* __restrict__ qkv,
                                                     __half* __restrict__ attn) {
    extern __shared__ char asmem[];
    int w = blockIdx.x, hg = blockIdx.y;
    int tid = threadIdx.x, wi = tid >> 5, lane = tid & 31;
    int head = hg * 4 + wi;

    __half* sh = (__half*)asmem + wi * AH_HALVES;
    int* sid = (int*)(asmem + ASM_SID);

    const __half* base = qkv + (size_t)w * 64 * 1536 + head * 32;
#pragma unroll
    for (int i = 0; i < 8; i++) {
        int c = lane + 32 * i;
        int r = c >> 2, sg = c & 3;
        const __half* src = base + (size_t)r * 1536 + sg * 8;
        cp16(&sh[r * 40 + sg * 8], src);
        cp16(&sh[2560 + r * 40 + sg * 8], src + 512);
        cp16(&sh[5120 + r * 40 + sg * 8], src + 1024);
    }
    cp_commit();
    if (tid < 64) {
        int wim = w & 63;
        int wy = wim >> 3, wx = wim & 7;
        int hh = wy * 8 + (tid >> 3), ww = wx * 8 + (tid & 7);
        int rh = (hh < 56) ? 0 : ((hh < 60) ? 1 : 2);
        int rw = (ww < 56) ? 0 : ((ww < 60) ? 1 : 2);
        sid[tid] = rh * 3 + rw;
    }
    cp_wait0();
    __syncthreads();

    int aRow = (lane & 7) + ((lane >> 3) & 1) * 8;
    int aCol = (lane >> 4) * 8;
    int bRow = (lane & 7) + (lane >> 4) * 8;
    int bCol = ((lane >> 3) & 1) * 8;

    uint32_t qa[4][2][4];
#pragma unroll
    for (int mi = 0; mi < 4; mi++)
#pragma unroll
        for (int ks = 0; ks < 2; ks++)
            ldm4(qa[mi][ks][0], qa[mi][ks][1], qa[mi][ks][2], qa[mi][ks][3],
                 &sh[(mi * 16 + aRow) * 40 + ks * 16 + aCol]);

    float sc[4][8][4];
#pragma unroll
    for (int mi = 0; mi < 4; mi++)
#pragma unroll
        for (int ni = 0; ni < 8; ni++)
#pragma unroll
            for (int j = 0; j < 4; j++) sc[mi][ni][j] = 0.0f;

    const __half* Ksh = sh + 2560;
#pragma unroll
    for (int nh = 0; nh < 2; nh++) {
        uint32_t kb[4][2][2];
#pragma unroll
        for (int nj2 = 0; nj2 < 2; nj2++)
#pragma unroll
            for (int ks = 0; ks < 2; ks++) {
                uint32_t q0, q1, q2, q3;
                ldm4(q0, q1, q2, q3,
                     &Ksh[(nh * 32 + nj2 * 16 + bRow) * 40 + ks * 16 + bCol]);
                kb[nj2 * 2][ks][0] = q0;     kb[nj2 * 2][ks][1] = q1;
                kb[nj2 * 2 + 1][ks][0] = q2; kb[nj2 * 2 + 1][ks][1] = q3;
            }
#pragma unroll
        for (int mi = 0; mi < 4; mi++)
#pragma unroll
            for (int f = 0; f < 4; f++)
#pragma unroll
                for (int ks = 0; ks < 2; ks++)
                    mma16816(sc[mi][nh * 4 + f][0], sc[mi][nh * 4 + f][1],
                             sc[mi][nh * 4 + f][2], sc[mi][nh * 4 + f][3],
                             qa[mi][ks][0], qa[mi][ks][1], qa[mi][ks][2], qa[mi][ks][3],
                             kb[f][ks][0], kb[f][ks][1]);
    }

    int rsub = lane >> 2;
    int cbase = (lane & 3) * 2;
    int cid[16];
#pragma unroll
    for (int ni = 0; ni < 8; ni++) {
        cid[2 * ni]     = sid[ni * 8 + cbase];
        cid[2 * ni + 1] = sid[ni * 8 + cbase + 1];
    }

    float inv1[4], inv2[4];
    uint32_t pa[4][4][4];
#pragma unroll
    for (int mi = 0; mi < 4; mi++) {
        int rid1 = sid[mi * 16 + rsub];
        int rid2 = sid[mi * 16 + rsub + 8];
#pragma unroll
        for (int ni = 0; ni < 8; ni++) {
            sc[mi][ni][0] = (cid[2 * ni]     == rid1) ? sc[mi][ni][0] * ATT_SCALE : -10000.0f;
            sc[mi][ni][1] = (cid[2 * ni + 1] == rid1) ? sc[mi][ni][1] * ATT_SCALE : -10000.0f;
            sc[mi][ni][2] = (cid[2 * ni]     == rid2) ? sc[mi][ni][2] * ATT_SCALE : -10000.0f;
            sc[mi][ni][3] = (cid[2 * ni + 1] == rid2) ? sc[mi][ni][3] * ATT_SCALE : -10000.0f;
        }
        float m1 = -1e30f, m2 = -1e30f;
#pragma unroll
        for (int ni = 0; ni < 8; ni++) {
            m1 = fmaxf(m1, fmaxf(sc[mi][ni][0], sc[mi][ni][1]));
            m2 = fmaxf(m2, fmaxf(sc[mi][ni][2], sc[mi][ni][3]));
        }
        m1 = fmaxf(m1, __shfl_xor_sync(0xffffffffu, m1, 1));
        m1 = fmaxf(m1, __shfl_xor_sync(0xffffffffu, m1, 2));
        m2 = fmaxf(m2, __shfl_xor_sync(0xffffffffu, m2, 1));
        m2 = fmaxf(m2, __shfl_xor_sync(0xffffffffu, m2, 2));
        float s1 = 0.0f, s2 = 0.0f;
#pragma unroll
        for (int ni = 0; ni < 8; ni++) {
            float e0 = __expf(sc[mi][ni][0] - m1);
            float e1 = __expf(sc[mi][ni][1] - m1);
            float e2 = __expf(sc[mi][ni][2] - m2);
            float e3 = __expf(sc[mi][ni][3] - m2);
            sc[mi][ni][0] = e0; sc[mi][ni][1] = e1;
            sc[mi][ni][2] = e2; sc[mi][ni][3] = e3;
            s1 += e0 + e1; s2 += e2 + e3;
        }
        s1 += __shfl_xor_sync(0xffffffffu, s1, 1);
        s1 += __shfl_xor_sync(0xffffffffu, s1, 2);
        s2 += __shfl_xor_sync(0xffffffffu, s2, 1);
        s2 += __shfl_xor_sync(0xffffffffu, s2, 2);
        inv1[mi] = 1.0f / s1;
        inv2[mi] = 1.0f / s2;
#pragma unroll
        for (int kj = 0; kj < 4; kj++) {
            __half2 h0 = __floats2half2_rn(sc[mi][2 * kj][0], sc[mi][2 * kj][1]);
            __half2 h1 = __floats2half2_rn(sc[mi][2 * kj][2], sc[mi][2 * kj][3]);
            __half2 h2 = __floats2half2_rn(sc[mi][2 * kj + 1][0], sc[mi][2 * kj + 1][1]);
            __half2 h3 = __floats2half2_rn(sc[mi][2 * kj + 1][2], sc[mi][2 * kj + 1][3]);
            pa[mi][kj][0] = *(uint32_t*)&h0;
            pa[mi][kj][1] = *(uint32_t*)&h1;
            pa[mi][kj][2] = *(uint32_t*)&h2;
            pa[mi][kj][3] = *(uint32_t*)&h3;
        }
    }

    float ot[4][4][4];
#pragma unroll
    for (int mi = 0; mi < 4; mi++)
#pragma unroll
        for (int nj = 0; nj < 4; nj++)
#pragma unroll
            for (int j = 0; j < 4; j++) ot[mi][nj][j] = 0.0f;

    const __half* Vsh = sh + 5120;
#pragma unroll
    for (int kj = 0; kj < 4; kj++) {
        uint32_t vb[4][2];
#pragma unroll
        for (int g = 0; g < 2; g++) {
            uint32_t q0, q1, q2, q3;
            ldm4t(q0, q1, q2, q3,
                  &Vsh[(kj * 16 + (lane & 7) + ((lane >> 3) & 1) * 8) * 40 +
                       g * 16 + (lane >> 4) * 8]);
            vb[2 * g][0] = q0;     vb[2 * g][1] = q1;
            vb[2 * g + 1][0] = q2; vb[2 * g + 1][1] = q3;
        }
#pragma unroll
        for (int mi = 0; mi < 4; mi++)
#pragma unroll
            for (int nj = 0; nj < 4; nj++)
                mma16816(ot[mi][nj][0], ot[mi][nj][1], ot[mi][nj][2], ot[mi][nj][3],
                         pa[mi][kj][0], pa[mi][kj][1], pa[mi][kj][2], pa[mi][kj][3],
                         vb[nj][0], vb[nj][1]);
    }

#pragma unroll
    for (int mi = 0; mi < 4; mi++) {
        __half* o1 = attn + (size_t)(w * 64 + mi * 16 + rsub) * 512 + head * 32 + cbase;
        __half* o2 = o1 + (size_t)8 * 512;
#pragma unroll
        for (int nj = 0; nj < 4; nj++) {
            *(__half2*)(o1 + nj * 8) =
                __floats2half2_rn(ot[mi][nj][0] * inv1[mi], ot[mi][nj][1] * inv1[mi]);
            *(__half2*)(o2 + nj * 8) =
                __floats2half2_rn(ot[mi][nj][2] * inv2[mi], ot[mi][nj][3] * inv2[mi]);
        }
    }
}

// ---------------------------------------------------------------------------
// Kernel 5: window reverse + roll(+4,+4) + residual + LN2
// ---------------------------------------------------------------------------
__global__ __launch_bounds__(128) void k_rev_ln2(const float* __restrict__ hs,
                                                 const float* __restrict__ proj,
                                                 const float* __restrict__ g,
                                                 const float* __restrict__ b,
                                                 float* __restrict__ x,
                                                 __half* __restrict__ hout) {
    int m = blockIdx.x;
    int bimg = m >> 12;
    int hw = m & 4095;
    int h0 = hw >> 6, w0 = hw & 63;
    int hr = (h0 + 64 - SHIFT) & 63, wr = (w0 + 64 - SHIFT) & 63;
    int wy = hr >> 3, rr = hr & 7, wx = wr >> 3, cc = wr & 7;
    int n = (bimg << 12) + ((wy * 8 + wx) << 6) + (rr * 8 + cc);

    int tid = threadIdx.x;
    float4 a = ((const float4*)(hs + (size_t)m * CDIM))[tid];
    float4 p = ((const float4*)(proj + (size_t)n * CDIM))[tid];
    float4 v = make_float4(a.x + p.x, a.y + p.y, a.z + p.z, a.w + p.w);
    ((float4*)(x + (size_t)m * CDIM))[tid] = v;

    float s  = v.x + v.y + v.z + v.w;
    float s2 = v.x * v.x + v.y * v.y + v.z * v.z + v.w * v.w;
#pragma unroll
    for (int o = 16; o; o >>= 1) {
        s  += __shfl_xor_sync(0xffffffffu, s,  o);
        s2 += __shfl_xor_sync(0xffffffffu, s2, o);
    }
    __shared__ float rs[4], rq[4];
    int warp = tid >> 5, lane = tid & 31;
    if (lane == 0) { rs[warp] = s; rq[warp] = s2; }
    __syncthreads();
    s  = rs[0] + rs[1] + rs[2] + rs[3];
    s2 = rq[0] + rq[1] + rq[2] + rq[3];
    float mean = s * (1.0f / 512.0f);
    float var  = s2 * (1.0f / 512.0f) - mean * mean;
    float rstd = rsqrtf(var + 1e-5f);

    int c = tid * 4;
    float4 gv = ((const float4*)g)[tid];
    float4 bv = ((const float4*)b)[tid];
    __half2* o = (__half2*)(hout + (size_t)m * CDIM + c);
    o[0] = __floats2half2_rn((v.x - mean) * rstd * gv.x + bv.x,
                             (v.y - mean) * rstd * gv.y + bv.y);
    o[1] = __floats2half2_rn((v.z - mean) * rstd * gv.z + bv.z,
                             (v.w - mean) * rstd * gv.w + bv.w);
}

// ---------------------------------------------------------------------------
// Host launcher
// ---------------------------------------------------------------------------
extern "C" void kernel_launch(void* const* d_in, const int* in_sizes, int n_in,
                              void* d_out, int out_size) {
    const float* hs   = (const float*)d_in[0];
    const float* Wqkv = (const float*)d_in[1];
    const float* bqkv = (const float*)d_in[2];
    const float* Wo   = (const float*)d_in[3];
    const float* bo   = (const float*)d_in[4];
    const float* ln1g = (const float*)d_in[5];
    const float* ln1b = (const float*)d_in[6];
    const float* ln2g = (const float*)d_in[7];
    const float* ln2b = (const float*)d_in[8];
    const float* W1   = (const float*)d_in[9];
    const float* b1   = (const float*)d_in[10];
    const float* W2   = (const float*)d_in[11];
    const float* b2   = (const float*)d_in[12];

    __half *xw, *qkv, *attn, *hbuf, *ff, *wqkvT, *woT, *w1T, *w2T;
    float *proj, *xbuf;
    cudaGetSymbolAddress((void**)&xw,    g_xw);
    cudaGetSymbolAddress((void**)&qkv,   g_qkv);
    cudaGetSymbolAddress((void**)&attn,  g_attn);
    cudaGetSymbolAddress((void**)&proj,  g_proj);
    cudaGetSymbolAddress((void**)&xbuf,  g_x);
    cudaGetSymbolAddress((void**)&hbuf,  g_h);
    cudaGetSymbolAddress((void**)&ff,    g_ff);
    cudaGetSymbolAddress((void**)&wqkvT, g_wqkvT);
    cudaGetSymbolAddress((void**)&woT,   g_woT);
    cudaGetSymbolAddress((void**)&w1T,   g_w1T);
    cudaGetSymbolAddress((void**)&w2T,   g_w2T);

    cudaFuncSetAttribute(gemm16<0>, cudaFuncAttributeMaxDynamicSharedMemorySize, GSM_TOTAL);
    cudaFuncSetAttribute(gemm16<1>, cudaFuncAttributeMaxDynamicSharedMemorySize, GSM_TOTAL);
    cudaFuncSetAttribute(gemm16<2>, cudaFuncAttributeMaxDynamicSharedMemorySize, GSM_TOTAL);
    cudaFuncSetAttribute(gemm16<3>, cudaFuncAttributeMaxDynamicSharedMemorySize, GSM_TOTAL);
    cudaFuncSetAttribute(k_attn_mma, cudaFuncAttributeMaxDynamicSharedMemorySize, ASM_TOTAL);

    // weight transposes (fp32 -> fp16, [K,N] -> [N,K])
    k_transpose<<<(512 * 1536 + 255) / 256, 256>>>(Wqkv, wqkvT, 512, 1536);
    k_transpose<<<(512 * 512  + 255) / 256, 256>>>(Wo,   woT,   512, 512);
    k_transpose<<<(512 * 2048 + 255) / 256, 256>>>(W1,   w1T,   512, 2048);
    k_transpose<<<(2048 * 512 + 255) / 256, 256>>>(W2,   w2T,   2048, 512);

    // 1. LN1 + shift + partition
    k_ln1<<<MTOK, 128>>>(hs, ln1g, ln1b, xw);

    // 2. QKV GEMM: [131072,512] x [512,1536] -> fp16
    gemm16<0><<<dim3(1536 / 128, MTOK / 128), 128, GSM_TOTAL>>>(
        xw, wqkvT, bqkv, nullptr, qkv, MTOK, 1536, 512);

    // 3. attention (HMMA, 1 warp per window-head)
    k_attn_mma<<<dim3(2048, 4), 128, ASM_TOTAL>>>(qkv, attn);

    // 4. out projection: [131072,512] x [512,512] -> fp32
    gemm16<1><<<dim3(512 / 128, MTOK / 128), 128, GSM_TOTAL>>>(
        attn, woT, bo, nullptr, proj, MTOK, 512, 512);

    // 5. reverse + residual + LN2
    k_rev_ln2<<<MTOK, 128>>>(hs, proj, ln2g, ln2b, xbuf, hbuf);

    // 6. MLP up + gelu: [131072,512] x [512,2048] -> fp16
    gemm16<2><<<dim3(2048 / 128, MTOK / 128), 128, GSM_TOTAL>>>(
        hbuf, w1T, b1, nullptr, ff, MTOK, 2048, 512);

    // 7. MLP down + residual: [131072,2048] x [2048,512] -> fp32 d_out
    gemm16<3><<<dim3(512 / 128, MTOK / 128), 128, GSM_TOTAL>>>(
        ff, w2T, b2, xbuf, d_out, MTOK, 512, 2048);
}

// round 7
// speedup vs baseline: 1.7143x; 1.0888x over previous
#include <cuda_runtime.h>
#include <cuda_fp16.h>
#include <cstdint>

// ---------------------------------------------------------------------------
// Problem constants
// ---------------------------------------------------------------------------
#define BATCH 32
#define CDIM  512
#define NHEAD 16
#define SHIFT 4
#define SEQ   64
#define HEADD 32
#define FFDIM 2048
#define MTOK  131072

// ---------------------------------------------------------------------------
// Scratch
// ---------------------------------------------------------------------------
__device__ __half g_xw  [ (size_t)MTOK * CDIM  ];
__device__ __half g_qkv [ (size_t)MTOK * 3*CDIM];
__device__ __half g_attn[ (size_t)MTOK * CDIM  ];
__device__ __half g_projh[(size_t)MTOK * CDIM ];
__device__ float  g_x   [ (size_t)MTOK * CDIM  ];
__device__ __half g_h   [ (size_t)MTOK * CDIM  ];
__device__ __half g_ff  [ (size_t)MTOK * FFDIM ];
__device__ __half g_wqkvT[3*CDIM * CDIM];
__device__ __half g_woT  [CDIM * CDIM];
__device__ __half g_w1T  [FFDIM * CDIM];
__device__ __half g_w2T  [CDIM * FFDIM];

// ---------------------------------------------------------------------------
// Helpers
// ---------------------------------------------------------------------------
__device__ __forceinline__ void cp16(void* smem, const void* gmem) {
    unsigned s = (unsigned)__cvta_generic_to_shared(smem);
    asm volatile("cp.async.cg.shared.global [%0], [%1], 16;\n" :: "r"(s), "l"(gmem));
}
__device__ __forceinline__ void cp_commit() { asm volatile("cp.async.commit_group;\n"); }
__device__ __forceinline__ void cp_wait1()  { asm volatile("cp.async.wait_group 1;\n"); }
__device__ __forceinline__ void cp_wait0()  { asm volatile("cp.async.wait_group 0;\n"); }

__device__ __forceinline__ void ldm4(uint32_t& r0, uint32_t& r1, uint32_t& r2, uint32_t& r3,
                                     const __half* p) {
    unsigned s = (unsigned)__cvta_generic_to_shared(p);
    asm volatile("ldmatrix.sync.aligned.m8n8.x4.shared.b16 {%0,%1,%2,%3},[%4];\n"
                 : "=r"(r0), "=r"(r1), "=r"(r2), "=r"(r3) : "r"(s));
}
__device__ __forceinline__ void ldm4t(uint32_t& r0, uint32_t& r1, uint32_t& r2, uint32_t& r3,
                                      const __half* p) {
    unsigned s = (unsigned)__cvta_generic_to_shared(p);
    asm volatile("ldmatrix.sync.aligned.m8n8.x4.trans.shared.b16 {%0,%1,%2,%3},[%4];\n"
                 : "=r"(r0), "=r"(r1), "=r"(r2), "=r"(r3) : "r"(s));
}
__device__ __forceinline__ void mma16816(float& c0, float& c1, float& c2, float& c3,
                                         uint32_t a0, uint32_t a1, uint32_t a2, uint32_t a3,
                                         uint32_t b0, uint32_t b1) {
    asm volatile("mma.sync.aligned.m16n8k16.row.col.f32.f16.f16.f32 "
                 "{%0,%1,%2,%3},{%4,%5,%6,%7},{%8,%9},{%0,%1,%2,%3};\n"
                 : "+f"(c0), "+f"(c1), "+f"(c2), "+f"(c3)
                 : "r"(a0), "r"(a1), "r"(a2), "r"(a3), "r"(b0), "r"(b1));
}
__device__ __forceinline__ float gelu_tanh(float x) {
    float x3 = x * x * x;
    return 0.5f * x * (1.0f + tanhf(0.7978845608028654f * (x + 0.044715f * x3)));
}

// ---------------------------------------------------------------------------
// Weight transpose + fp32->fp16 convert: W[K][N] -> Wt[N][K]
// ---------------------------------------------------------------------------
__global__ void k_transpose(const float* __restrict__ W, __half* __restrict__ Wt,
                            int K, int N) {
    int i = blockIdx.x * 256 + threadIdx.x;
    if (i >= K * N) return;
    int n = i / K;
    int k = i - n * K;
    Wt[i] = __float2half(W[(size_t)k * N + n]);
}

// ---------------------------------------------------------------------------
// Kernel 1: LN1 + roll(-4,-4) + window partition
// ---------------------------------------------------------------------------
__global__ __launch_bounds__(128) void k_ln1(const float* __restrict__ hs,
                                             const float* __restrict__ g,
                                             const float* __restrict__ b,
                                             __half* __restrict__ xw) {
    int n    = blockIdx.x;
    int bimg = n >> 12;
    int rem  = n & 4095;
    int wid  = rem >> 6, t = rem & 63;
    int wy = wid >> 3, wx = wid & 7;
    int hr = wy * 8 + (t >> 3), wr = wx * 8 + (t & 7);
    int h0 = (hr + SHIFT) & 63, w0 = (wr + SHIFT) & 63;
    size_t src = ((size_t)(bimg << 12) + (h0 << 6) + w0) * CDIM;

    int tid = threadIdx.x;
    float4 v = ((const float4*)(hs + src))[tid];
    float s  = v.x + v.y + v.z + v.w;
    float s2 = v.x * v.x + v.y * v.y + v.z * v.z + v.w * v.w;
#pragma unroll
    for (int o = 16; o; o >>= 1) {
        s  += __shfl_xor_sync(0xffffffffu, s,  o);
        s2 += __shfl_xor_sync(0xffffffffu, s2, o);
    }
    __shared__ float rs[4], rq[4];
    int warp = tid >> 5, lane = tid & 31;
    if (lane == 0) { rs[warp] = s; rq[warp] = s2; }
    __syncthreads();
    s  = rs[0] + rs[1] + rs[2] + rs[3];
    s2 = rq[0] + rq[1] + rq[2] + rq[3];
    float mean = s * (1.0f / 512.0f);
    float var  = s2 * (1.0f / 512.0f) - mean * mean;
    float rstd = rsqrtf(var + 1e-5f);

    int c = tid * 4;
    float4 gv = ((const float4*)g)[tid];
    float4 bv = ((const float4*)b)[tid];
    __half2* o = (__half2*)(xw + (size_t)n * CDIM + c);
    o[0] = __floats2half2_rn((v.x - mean) * rstd * gv.x + bv.x,
                             (v.y - mean) * rstd * gv.y + bv.y);
    o[1] = __floats2half2_rn((v.z - mean) * rstd * gv.z + bv.z,
                             (v.w - mean) * rstd * gv.w + bv.w);
}

// ---------------------------------------------------------------------------
// HMMA GEMM: 128x128 CTA tile, 128 threads (4 warps, 64x64 warp tiles),
// BK=32, 4-stage smem ring + register fragment double-buffer, 2 CTAs/SM.
// EPI: 0 +bias->fp16 | 2 gelu->fp16 | 3 +res->fp32
// ---------------------------------------------------------------------------
#define KW    40
#define ROWB  80
#define STGB  (128 * ROWB)
#define NSTG  4
#define GSM_BIAS 0
#define GSM_A    1024
#define GSM_B    (GSM_A + NSTG * STGB)
#define GSM_TOTAL (GSM_B + NSTG * STGB)

__device__ __forceinline__ void g4_load(char* smem, const __half* A, const __half* Bt,
                                        size_t aBase, size_t bBase, int K,
                                        int st, int ko, int tid) {
    char* pa = smem + GSM_A + st * STGB;
    char* pb = smem + GSM_B + st * STGB;
#pragma unroll
    for (int j = 0; j < 4; j++) {
        int c = tid + 128 * j;
        int r = c >> 2, sg = c & 3;
        cp16(pa + r * ROWB + sg * 16, A + aBase + (size_t)r * K + ko + sg * 8);
        cp16(pb + r * ROWB + sg * 16, Bt + bBase + (size_t)r * K + ko + sg * 8);
    }
}

template <int EPI>
__global__ __launch_bounds__(128, 2) void gemm16(const __half* __restrict__ A,
                                                 const __half* __restrict__ Bt,
                                                 const float* __restrict__ bias,
                                                 const float* __restrict__ res,
                                                 void* __restrict__ outp,
                                                 int M, int N, int K) {
    extern __shared__ char smem[];
    int tid = threadIdx.x;
    int bx = blockIdx.x, by = blockIdx.y;
    size_t aBase = (size_t)by * 128 * K;
    size_t bBase = (size_t)bx * 128 * K;

    ((float*)(smem + GSM_BIAS))[tid] = bias[bx * 128 + tid];

    int niter = K >> 5;

#pragma unroll
    for (int st = 0; st < 3; st++) {
        g4_load(smem, A, Bt, aBase, bBase, K, st, st << 5, tid);
        cp_commit();
    }

    int warp = tid >> 5, lane = tid & 31;
    int wm = warp >> 1, wn = warp & 1;          // 2x2 warps; warp tile 64x64

    float acc[4][8][4];
#pragma unroll
    for (int mi = 0; mi < 4; mi++)
#pragma unroll
        for (int ni = 0; ni < 8; ni++)
#pragma unroll
            for (int j = 0; j < 4; j++) acc[mi][ni][j] = 0.0f;

    int aRow = wm * 64 + (lane & 7) + ((lane >> 3) & 1) * 8;
    int aCol = (lane >> 4) * 8;
    int bRow = wn * 64 + (lane & 7) + (lane >> 4) * 8;
    int bCol = ((lane >> 3) & 1) * 8;

    uint32_t fa[2][4][4];
    uint32_t fb[2][8][2];

    cp_wait1();                   // stages 0,1 resident
    __syncthreads();

    // preload stage 0, ks=0 fragments
    {
        const __half* sa = (const __half*)(smem + GSM_A);
        const __half* sb = (const __half*)(smem + GSM_B);
#pragma unroll
        for (int mi = 0; mi < 4; mi++)
            ldm4(fa[0][mi][0], fa[0][mi][1], fa[0][mi][2], fa[0][mi][3],
                 sa + (size_t)(aRow + mi * 16) * KW + aCol);
#pragma unroll
        for (int nj = 0; nj < 4; nj++) {
            uint32_t q0, q1, q2, q3;
            ldm4(q0, q1, q2, q3, sb + (size_t)(bRow + nj * 16) * KW + bCol);
            fb[0][nj * 2][0] = q0; fb[0][nj * 2][1] = q1;
            fb[0][nj * 2 + 1][0] = q2; fb[0][nj * 2 + 1][1] = q3;
        }
    }

    for (int it = 0; it < niter; ++it) {
        int st = it & 3;
        const __half* sa = (const __half*)(smem + GSM_A + st * STGB);
        const __half* sb = (const __half*)(smem + GSM_B + st * STGB);

        // prefetch ks=1 fragments while computing ks=0
#pragma unroll
        for (int mi = 0; mi < 4; mi++)
            ldm4(fa[1][mi][0], fa[1][mi][1], fa[1][mi][2], fa[1][mi][3],
                 sa + (size_t)(aRow + mi * 16) * KW + 16 + aCol);
#pragma unroll
        for (int nj = 0; nj < 4; nj++) {
            uint32_t q0, q1, q2, q3;
            ldm4(q0, q1, q2, q3, sb + (size_t)(bRow + nj * 16) * KW + 16 + bCol);
            fb[1][nj * 2][0] = q0; fb[1][nj * 2][1] = q1;
            fb[1][nj * 2 + 1][0] = q2; fb[1][nj * 2 + 1][1] = q3;
        }
#pragma unroll
        for (int mi = 0; mi < 4; mi++)
#pragma unroll
            for (int ni = 0; ni < 8; ni++)
                mma16816(acc[mi][ni][0], acc[mi][ni][1], acc[mi][ni][2], acc[mi][ni][3],
                         fa[0][mi][0], fa[0][mi][1], fa[0][mi][2], fa[0][mi][3],
                         fb[0][ni][0], fb[0][ni][1]);

        // ring maintenance; stage it+1 guaranteed resident after wait1
        cp_wait1();
        __syncthreads();
        if (it + 3 < niter)
            g4_load(smem, A, Bt, aBase, bBase, K, (it + 3) & 3, (it + 3) << 5, tid);
        cp_commit();

        // prefetch next stage ks=0 fragments while computing ks=1
        if (it + 1 < niter) {
            int sn = (it + 1) & 3;
            const __half* sa2 = (const __half*)(smem + GSM_A + sn * STGB);
            const __half* sb2 = (const __half*)(smem + GSM_B + sn * STGB);
#pragma unroll
            for (int mi = 0; mi < 4; mi++)
                ldm4(fa[0][mi][0], fa[0][mi][1], fa[0][mi][2], fa[0][mi][3],
                     sa2 + (size_t)(aRow + mi * 16) * KW + aCol);
#pragma unroll
            for (int nj = 0; nj < 4; nj++) {
                uint32_t q0, q1, q2, q3;
                ldm4(q0, q1, q2, q3, sb2 + (size_t)(bRow + nj * 16) * KW + bCol);
                fb[0][nj * 2][0] = q0; fb[0][nj * 2][1] = q1;
                fb[0][nj * 2 + 1][0] = q2; fb[0][nj * 2 + 1][1] = q3;
            }
        }
#pragma unroll
        for (int mi = 0; mi < 4; mi++)
#pragma unroll
            for (int ni = 0; ni < 8; ni++)
                mma16816(acc[mi][ni][0], acc[mi][ni][1], acc[mi][ni][2], acc[mi][ni][3],
                         fa[1][mi][0], fa[1][mi][1], fa[1][mi][2], fa[1][mi][3],
                         fb[1][ni][0], fb[1][ni][1]);
    }

    // epilogue
    const float* sbias = (const float*)(smem + GSM_BIAS);
    int gm0 = by * 128 + wm * 64;
    int gn0 = bx * 128 + wn * 64;
    int ln0 = wn * 64;
#pragma unroll
    for (int mi = 0; mi < 4; mi++) {
#pragma unroll
        for (int ni = 0; ni < 8; ni++) {
            int row = gm0 + mi * 16 + (lane >> 2);
            int col = gn0 + ni * 8 + (lane & 3) * 2;
            int lcol = ln0 + ni * 8 + (lane & 3) * 2;
            float bv0 = sbias[lcol], bv1 = sbias[lcol + 1];
#pragma unroll
            for (int hf = 0; hf < 2; hf++) {
                int gr = row + hf * 8;
                float v0 = acc[mi][ni][hf * 2 + 0] + bv0;
                float v1 = acc[mi][ni][hf * 2 + 1] + bv1;
                size_t off = (size_t)gr * N + col;
                if constexpr (EPI == 0) {
                    *(__half2*)((__half*)outp + off) = __floats2half2_rn(v0, v1);
                } else if constexpr (EPI == 2) {
                    *(__half2*)((__half*)outp + off) =
                        __floats2half2_rn(gelu_tanh(v0), gelu_tanh(v1));
                } else {
                    v0 += res[off];
                    v1 += res[off + 1];
                    *(float2*)((float*)outp + off) = make_float2(v0, v1);
                }
            }
        }
    }
}

// ---------------------------------------------------------------------------
// Kernel 3: HMMA attention. One WARP per (window, head); block = 4 heads.
// ---------------------------------------------------------------------------
#define ATT_SCALE 0.17677669529663687f
#define AH_HALVES 7680
#define ASM_SID   61440
#define ASM_TOTAL 61696

__global__ __launch_bounds__(128, 2) void k_attn_mma(const __half* __restrict__ qkv,
                                                     __half* __restrict__ attn) {
    extern __shared__ char asmem[];
    int w = blockIdx.x, hg = blockIdx.y;
    int tid = threadIdx.x, wi = tid >> 5, lane = tid & 31;
    int head = hg * 4 + wi;

    __half* sh = (__half*)asmem + wi * AH_HALVES;
    int* sid = (int*)(asmem + ASM_SID);

    const __half* base = qkv + (size_t)w * 64 * 1536 + head * 32;
#pragma unroll
    for (int i = 0; i < 8; i++) {
        int c = lane + 32 * i;
        int r = c >> 2, sg = c & 3;
        const __half* src = base + (size_t)r * 1536 + sg * 8;
        cp16(&sh[r * 40 + sg * 8], src);
        cp16(&sh[2560 + r * 40 + sg * 8], src + 512);
        cp16(&sh[5120 + r * 40 + sg * 8], src + 1024);
    }
    cp_commit();
    if (tid < 64) {
        int wim = w & 63;
        int wy = wim >> 3, wx = wim & 7;
        int hh = wy * 8 + (tid >> 3), ww = wx * 8 + (tid & 7);
        int rh = (hh < 56) ? 0 : ((hh < 60) ? 1 : 2);
        int rw = (ww < 56) ? 0 : ((ww < 60) ? 1 : 2);
        sid[tid] = rh * 3 + rw;
    }
    cp_wait0();
    __syncthreads();

    int aRow = (lane & 7) + ((lane >> 3) & 1) * 8;
    int aCol = (lane >> 4) * 8;
    int bRow = (lane & 7) + (lane >> 4) * 8;
    int bCol = ((lane >> 3) & 1) * 8;

    uint32_t qa[4][2][4];
#pragma unroll
    for (int mi = 0; mi < 4; mi++)
#pragma unroll
        for (int ks = 0; ks < 2; ks++)
            ldm4(qa[mi][ks][0], qa[mi][ks][1], qa[mi][ks][2], qa[mi][ks][3],
                 &sh[(mi * 16 + aRow) * 40 + ks * 16 + aCol]);

    float sc[4][8][4];
#pragma unroll
    for (int mi = 0; mi < 4; mi++)
#pragma unroll
        for (int ni = 0; ni < 8; ni++)
#pragma unroll
            for (int j = 0; j < 4; j++) sc[mi][ni][j] = 0.0f;

    const __half* Ksh = sh + 2560;
#pragma unroll
    for (int nh = 0; nh < 2; nh++) {
        uint32_t kb[4][2][2];
#pragma unroll
        for (int nj2 = 0; nj2 < 2; nj2++)
#pragma unroll
            for (int ks = 0; ks < 2; ks++) {
                uint32_t q0, q1, q2, q3;
                ldm4(q0, q1, q2, q3,
                     &Ksh[(nh * 32 + nj2 * 16 + bRow) * 40 + ks * 16 + bCol]);
                kb[nj2 * 2][ks][0] = q0;     kb[nj2 * 2][ks][1] = q1;
                kb[nj2 * 2 + 1][ks][0] = q2; kb[nj2 * 2 + 1][ks][1] = q3;
            }
#pragma unroll
        for (int mi = 0; mi < 4; mi++)
#pragma unroll
            for (int f = 0; f < 4; f++)
#pragma unroll
                for (int ks = 0; ks < 2; ks++)
                    mma16816(sc[mi][nh * 4 + f][0], sc[mi][nh * 4 + f][1],
                             sc[mi][nh * 4 + f][2], sc[mi][nh * 4 + f][3],
                             qa[mi][ks][0], qa[mi][ks][1], qa[mi][ks][2], qa[mi][ks][3],
                             kb[f][ks][0], kb[f][ks][1]);
    }

    int rsub = lane >> 2;
    int cbase = (lane & 3) * 2;
    int cid[16];
#pragma unroll
    for (int ni = 0; ni < 8; ni++) {
        cid[2 * ni]     = sid[ni * 8 + cbase];
        cid[2 * ni + 1] = sid[ni * 8 + cbase + 1];
    }

    float inv1[4], inv2[4];
    uint32_t pa[4][4][4];
#pragma unroll
    for (int mi = 0; mi < 4; mi++) {
        int rid1 = sid[mi * 16 + rsub];
        int rid2 = sid[mi * 16 + rsub + 8];
#pragma unroll
        for (int ni = 0; ni < 8; ni++) {
            sc[mi][ni][0] = (cid[2 * ni]     == rid1) ? sc[mi][ni][0] * ATT_SCALE : -10000.0f;
            sc[mi][ni][1] = (cid[2 * ni + 1] == rid1) ? sc[mi][ni][1] * ATT_SCALE : -10000.0f;
            sc[mi][ni][2] = (cid[2 * ni]     == rid2) ? sc[mi][ni][2] * ATT_SCALE : -10000.0f;
            sc[mi][ni][3] = (cid[2 * ni + 1] == rid2) ? sc[mi][ni][3] * ATT_SCALE : -10000.0f;
        }
        float m1 = -1e30f, m2 = -1e30f;
#pragma unroll
        for (int ni = 0; ni < 8; ni++) {
            m1 = fmaxf(m1, fmaxf(sc[mi][ni][0], sc[mi][ni][1]));
            m2 = fmaxf(m2, fmaxf(sc[mi][ni][2], sc[mi][ni][3]));
        }
        m1 = fmaxf(m1, __shfl_xor_sync(0xffffffffu, m1, 1));
        m1 = fmaxf(m1, __shfl_xor_sync(0xffffffffu, m1, 2));
        m2 = fmaxf(m2, __shfl_xor_sync(0xffffffffu, m2, 1));
        m2 = fmaxf(m2, __shfl_xor_sync(0xffffffffu, m2, 2));
        float s1 = 0.0f, s2 = 0.0f;
#pragma unroll
        for (int ni = 0; ni < 8; ni++) {
            float e0 = __expf(sc[mi][ni][0] - m1);
            float e1 = __expf(sc[mi][ni][1] - m1);
            float e2 = __expf(sc[mi][ni][2] - m2);
            float e3 = __expf(sc[mi][ni][3] - m2);
            sc[mi][ni][0] = e0; sc[mi][ni][1] = e1;
            sc[mi][ni][2] = e2; sc[mi][ni][3] = e3;
            s1 += e0 + e1; s2 += e2 + e3;
        }
        s1 += __shfl_xor_sync(0xffffffffu, s1, 1);
        s1 += __shfl_xor_sync(0xffffffffu, s1, 2);
        s2 += __shfl_xor_sync(0xffffffffu, s2, 1);
        s2 += __shfl_xor_sync(0xffffffffu, s2, 2);
        inv1[mi] = 1.0f / s1;
        inv2[mi] = 1.0f / s2;
#pragma unroll
        for (int kj = 0; kj < 4; kj++) {
            __half2 h0 = __floats2half2_rn(sc[mi][2 * kj][0], sc[mi][2 * kj][1]);
            __half2 h1 = __floats2half2_rn(sc[mi][2 * kj][2], sc[mi][2 * kj][3]);
            __half2 h2 = __floats2half2_rn(sc[mi][2 * kj + 1][0], sc[mi][2 * kj + 1][1]);
            __half2 h3 = __floats2half2_rn(sc[mi][2 * kj + 1][2], sc[mi][2 * kj + 1][3]);
            pa[mi][kj][0] = *(uint32_t*)&h0;
            pa[mi][kj][1] = *(uint32_t*)&h1;
            pa[mi][kj][2] = *(uint32_t*)&h2;
            pa[mi][kj][3] = *(uint32_t*)&h3;
        }
    }

    float ot[4][4][4];
#pragma unroll
    for (int mi = 0; mi < 4; mi++)
#pragma unroll
        for (int nj = 0; nj < 4; nj++)
#pragma unroll
            for (int j = 0; j < 4; j++) ot[mi][nj][j] = 0.0f;

    const __half* Vsh = sh + 5120;
#pragma unroll
    for (int kj = 0; kj < 4; kj++) {
        uint32_t vb[4][2];
#pragma unroll
        for (int g = 0; g < 2; g++) {
            uint32_t q0, q1, q2, q3;
            ldm4t(q0, q1, q2, q3,
                  &Vsh[(kj * 16 + (lane & 7) + ((lane >> 3) & 1) * 8) * 40 +
                       g * 16 + (lane >> 4) * 8]);
            vb[2 * g][0] = q0;     vb[2 * g][1] = q1;
            vb[2 * g + 1][0] = q2; vb[2 * g + 1][1] = q3;
        }
#pragma unroll
        for (int mi = 0; mi < 4; mi++)
#pragma unroll
            for (int nj = 0; nj < 4; nj++)
                mma16816(ot[mi][nj][0], ot[mi][nj][1], ot[mi][nj][2], ot[mi][nj][3],
                         pa[mi][kj][0], pa[mi][kj][1], pa[mi][kj][2], pa[mi][kj][3],
                         vb[nj][0], vb[nj][1]);
    }

#pragma unroll
    for (int mi = 0; mi < 4; mi++) {
        __half* o1 = attn + (size_t)(w * 64 + mi * 16 + rsub) * 512 + head * 32 + cbase;
        __half* o2 = o1 + (size_t)8 * 512;
#pragma unroll
        for (int nj = 0; nj < 4; nj++) {
            *(__half2*)(o1 + nj * 8) =
                __floats2half2_rn(ot[mi][nj][0] * inv1[mi], ot[mi][nj][1] * inv1[mi]);
            *(__half2*)(o2 + nj * 8) =
                __floats2half2_rn(ot[mi][nj][2] * inv2[mi], ot[mi][nj][3] * inv2[mi]);
        }
    }
}

// ---------------------------------------------------------------------------
// Kernel 5: window reverse + roll(+4,+4) + residual + LN2 (proj now fp16)
// ---------------------------------------------------------------------------
__global__ __launch_bounds__(128) void k_rev_ln2(const float* __restrict__ hs,
                                                 const __half* __restrict__ proj,
                                                 const float* __restrict__ g,
                                                 const float* __restrict__ b,
                                                 float* __restrict__ x,
                                                 __half* __restrict__ hout) {
    int m = blockIdx.x;
    int bimg = m >> 12;
    int hw = m & 4095;
    int h0 = hw >> 6, w0 = hw & 63;
    int hr = (h0 + 64 - SHIFT) & 63, wr = (w0 + 64 - SHIFT) & 63;
    int wy = hr >> 3, rr = hr & 7, wx = wr >> 3, cc = wr & 7;
    int n = (bimg << 12) + ((wy * 8 + wx) << 6) + (rr * 8 + cc);

    int tid = threadIdx.x;
    float4 a = ((const float4*)(hs + (size_t)m * CDIM))[tid];
    uint2 ph = ((const uint2*)(proj + (size_t)n * CDIM))[tid];
    float2 p0 = __half22float2(*(__half2*)&ph.x);
    float2 p1 = __half22float2(*(__half2*)&ph.y);
    float4 v = make_float4(a.x + p0.x, a.y + p0.y, a.z + p1.x, a.w + p1.y);
    ((float4*)(x + (size_t)m * CDIM))[tid] = v;

    float s  = v.x + v.y + v.z + v.w;
    float s2 = v.x * v.x + v.y * v.y + v.z * v.z + v.w * v.w;
#pragma unroll
    for (int o = 16; o; o >>= 1) {
        s  += __shfl_xor_sync(0xffffffffu, s,  o);
        s2 += __shfl_xor_sync(0xffffffffu, s2, o);
    }
    __shared__ float rs[4], rq[4];
    int warp = tid >> 5, lane = tid & 31;
    if (lane == 0) { rs[warp] = s; rq[warp] = s2; }
    __syncthreads();
    s  = rs[0] + rs[1] + rs[2] + rs[3];
    s2 = rq[0] + rq[1] + rq[2] + rq[3];
    float mean = s * (1.0f / 512.0f);
    float var  = s2 * (1.0f / 512.0f) - mean * mean;
    float rstd = rsqrtf(var + 1e-5f);

    int c = tid * 4;
    float4 gv = ((const float4*)g)[tid];
    float4 bv = ((const float4*)b)[tid];
    __half2* o = (__half2*)(hout + (size_t)m * CDIM + c);
    o[0] = __floats2half2_rn((v.x - mean) * rstd * gv.x + bv.x,
                             (v.y - mean) * rstd * gv.y + bv.y);
    o[1] = __floats2half2_rn((v.z - mean) * rstd * gv.z + bv.z,
                             (v.w - mean) * rstd * gv.w + bv.w);
}

// ---------------------------------------------------------------------------
// Host launcher
// ---------------------------------------------------------------------------
extern "C" void kernel_launch(void* const* d_in, const int* in_sizes, int n_in,
                              void* d_out, int out_size) {
    const float* hs   = (const float*)d_in[0];
    const float* Wqkv = (const float*)d_in[1];
    const float* bqkv = (const float*)d_in[2];
    const float* Wo   = (const float*)d_in[3];
    const float* bo   = (const float*)d_in[4];
    const float* ln1g = (const float*)d_in[5];
    const float* ln1b = (const float*)d_in[6];
    const float* ln2g = (const float*)d_in[7];
    const float* ln2b = (const float*)d_in[8];
    const float* W1   = (const float*)d_in[9];
    const float* b1   = (const float*)d_in[10];
    const float* W2   = (const float*)d_in[11];
    const float* b2   = (const float*)d_in[12];

    __half *xw, *qkv, *attn, *projh, *hbuf, *ff, *wqkvT, *woT, *w1T, *w2T;
    float *xbuf;
    cudaGetSymbolAddress((void**)&xw,    g_xw);
    cudaGetSymbolAddress((void**)&qkv,   g_qkv);
    cudaGetSymbolAddress((void**)&attn,  g_attn);
    cudaGetSymbolAddress((void**)&projh, g_projh);
    cudaGetSymbolAddress((void**)&xbuf,  g_x);
    cudaGetSymbolAddress((void**)&hbuf,  g_h);
    cudaGetSymbolAddress((void**)&ff,    g_ff);
    cudaGetSymbolAddress((void**)&wqkvT, g_wqkvT);
    cudaGetSymbolAddress((void**)&woT,   g_woT);
    cudaGetSymbolAddress((void**)&w1T,   g_w1T);
    cudaGetSymbolAddress((void**)&w2T,   g_w2T);

    cudaFuncSetAttribute(gemm16<0>, cudaFuncAttributeMaxDynamicSharedMemorySize, GSM_TOTAL);
    cudaFuncSetAttribute(gemm16<2>, cudaFuncAttributeMaxDynamicSharedMemorySize, GSM_TOTAL);
    cudaFuncSetAttribute(gemm16<3>, cudaFuncAttributeMaxDynamicSharedMemorySize, GSM_TOTAL);
    cudaFuncSetAttribute(k_attn_mma, cudaFuncAttributeMaxDynamicSharedMemorySize, ASM_TOTAL);

    // weight transposes (fp32 -> fp16, [K,N] -> [N,K])
    k_transpose<<<(512 * 1536 + 255) / 256, 256>>>(Wqkv, wqkvT, 512, 1536);
    k_transpose<<<(512 * 512  + 255) / 256, 256>>>(Wo,   woT,   512, 512);
    k_transpose<<<(512 * 2048 + 255) / 256, 256>>>(W1,   w1T,   512, 2048);
    k_transpose<<<(2048 * 512 + 255) / 256, 256>>>(W2,   w2T,   2048, 512);

    // 1. LN1 + shift + partition
    k_ln1<<<MTOK, 128>>>(hs, ln1g, ln1b, xw);

    // 2. QKV GEMM: [131072,512] x [512,1536] -> fp16
    gemm16<0><<<dim3(1536 / 128, MTOK / 128), 128, GSM_TOTAL>>>(
        xw, wqkvT, bqkv, nullptr, qkv, MTOK, 1536, 512);

    // 3. attention (HMMA, 1 warp per window-head)
    k_attn_mma<<<dim3(2048, 4), 128, ASM_TOTAL>>>(qkv, attn);

    // 4. out projection: [131072,512] x [512,512] -> fp16
    gemm16<0><<<dim3(512 / 128, MTOK / 128), 128, GSM_TOTAL>>>(
        attn, woT, bo, nullptr, projh, MTOK, 512, 512);

    // 5. reverse + residual + LN2
    k_rev_ln2<<<MTOK, 128>>>(hs, projh, ln2g, ln2b, xbuf, hbuf);

    // 6. MLP up + gelu: [131072,512] x [512,2048] -> fp16
    gemm16<2><<<dim3(2048 / 128, MTOK / 128), 128, GSM_TOTAL>>>(
        hbuf, w1T, b1, nullptr, ff, MTOK, 2048, 512);

    // 7. MLP down + residual: [131072,2048] x [2048,512] -> fp32 d_out
    gemm16<3><<<dim3(512 / 128, MTOK / 128), 128, GSM_TOTAL>>>(
        ff, w2T, b2, xbuf, d_out, MTOK, 512, 2048);
}